// round 1
// baseline (speedup 1.0000x reference)
#include <cuda_runtime.h>

#define NRES 320
#define CDIM 128
#define NH 4
#define DH 32
#define NN (NRES*NRES)

// -------- device scratch (no allocation allowed) --------
__device__ float g_q   [(size_t)NRES*NH*NRES*DH];   // [i][h][j][d]
__device__ float g_k   [(size_t)NRES*NH*NRES*DH];
__device__ float g_v   [(size_t)NRES*NH*NRES*DH];
__device__ float g_gate[(size_t)NRES*NH*NRES*DH];   // sigmoid already applied
__device__ float g_og  [(size_t)NN*CDIM];           // gated attention output [i][j][h*32+d]
__device__ float g_bias[(size_t)NH*NN];             // tri bias [h][i][j]

// =====================================================================
// Kernel A: layernorm + q/k/v/gate projections + triangle bias
// block = 256 threads, 32 rows of (i,j)
// =====================================================================
__global__ __launch_bounds__(256, 1) void kA(
    const float* __restrict__ x,   const float* __restrict__ lng,
    const float* __restrict__ lnb, const float* __restrict__ wb,
    const float* __restrict__ wq,  const float* __restrict__ wk,
    const float* __restrict__ wv,  const float* __restrict__ wg,
    const float* __restrict__ bg)
{
    __shared__ float xsT[CDIM*36];     // transposed normalized tile: [c][row], stride 36
    __shared__ float sg[CDIM], sb[CDIM];

    int tid = threadIdx.x;
    int Rb  = blockIdx.x * 32;

    if (tid < CDIM) { sg[tid] = lng[tid]; sb[tid] = lnb[tid]; }

    // ---- layernorm: 8 threads per row ----
    int row = tid >> 3, sub = tid & 7;
    float xv[16];
    const float* xr = x + (size_t)(Rb + row) * CDIM + sub * 16;
    #pragma unroll
    for (int m4 = 0; m4 < 4; m4++) {
        float4 t = *(const float4*)(xr + m4 * 4);
        xv[m4*4+0] = t.x; xv[m4*4+1] = t.y; xv[m4*4+2] = t.z; xv[m4*4+3] = t.w;
    }
    float sum = 0.f, sq = 0.f;
    #pragma unroll
    for (int m = 0; m < 16; m++) { sum += xv[m]; sq += xv[m]*xv[m]; }
    #pragma unroll
    for (int off = 4; off >= 1; off >>= 1) {
        sum += __shfl_xor_sync(0xffffffffu, sum, off, 8);
        sq  += __shfl_xor_sync(0xffffffffu, sq,  off, 8);
    }
    float mu = sum * (1.f / CDIM);
    float rs = rsqrtf(sq * (1.f / CDIM) - mu * mu + 1e-5f);

    __syncthreads();   // sg/sb visible
    #pragma unroll
    for (int m = 0; m < 16; m++) {
        int c = sub * 16 + m;
        xsT[c * 36 + row] = (xv[m] - mu) * rs * sg[c] + sb[c];
    }
    __syncthreads();

    // ---- projections: 32x128 tile, 4x4 register tile per thread ----
    int tx = tid & 31, ty = tid >> 5;
    int col4 = tx * 4, row4 = ty * 4;
    int hh = col4 >> 5, dd = col4 & 31;

    #pragma unroll 1
    for (int s = 0; s < 4; s++) {
        const float* W = (s == 0) ? wq : (s == 1) ? wk : (s == 2) ? wv : wg;
        float acc[4][4] = {};
        #pragma unroll 4
        for (int kk = 0; kk < CDIM; kk++) {
            float4 a = *(const float4*)&xsT[kk * 36 + row4];
            float4 b = *(const float4*)&W[kk * CDIM + col4];
            float av[4] = {a.x, a.y, a.z, a.w};
            float bv[4] = {b.x, b.y, b.z, b.w};
            #pragma unroll
            for (int r = 0; r < 4; r++)
                #pragma unroll
                for (int c = 0; c < 4; c++)
                    acc[r][c] += av[r] * bv[c];
        }
        if (s == 0) {   // q scaled by 1/sqrt(32)
            #pragma unroll
            for (int r = 0; r < 4; r++)
                #pragma unroll
                for (int c = 0; c < 4; c++)
                    acc[r][c] *= 0.17677669529663687f;
        }
        if (s == 3) {   // gate = sigmoid(. + bg)
            float4 bgv = *(const float4*)&bg[col4];
            float bvv[4] = {bgv.x, bgv.y, bgv.z, bgv.w};
            #pragma unroll
            for (int r = 0; r < 4; r++)
                #pragma unroll
                for (int c = 0; c < 4; c++)
                    acc[r][c] = 1.f / (1.f + __expf(-(acc[r][c] + bvv[c])));
        }
        float* dst = (s == 0) ? g_q : (s == 1) ? g_k : (s == 2) ? g_v : g_gate;
        #pragma unroll
        for (int r = 0; r < 4; r++) {
            int R = Rb + row4 + r;
            int i = R / NRES, j = R - i * NRES;
            float4 o4 = make_float4(acc[r][0], acc[r][1], acc[r][2], acc[r][3]);
            *(float4*)&dst[(((size_t)i * NH + hh) * NRES + j) * DH + dd] = o4;
        }
    }

    // ---- triangle bias: 32 rows x 4 heads ----
    if (tid < CDIM) {
        int r = tid >> 2, h2 = tid & 3;
        float acc = 0.f;
        #pragma unroll 8
        for (int kk = 0; kk < CDIM; kk++)
            acc += xsT[kk * 36 + r] * wb[kk * NH + h2];
        g_bias[(size_t)h2 * NN + Rb + r] = acc;
    }
}

// =====================================================================
// Kernel B: attention per (i,h). 256 threads, 8 warps, 8 queries/warp/pass
// =====================================================================
#define SMEM_B ((320*36*2 + 8*320*12 + 8*8*36 + 320) * 4)

__global__ __launch_bounds__(256, 1) void kB(const float* __restrict__ mask)
{
    extern __shared__ float sm[];
    float* ks  = sm;                    // [320][36]
    float* vs  = ks  + 320 * 36;        // [320][36]
    float* am  = vs  + 320 * 36;        // per warp [320][12]  (a[kk][q])
    float* qsm = am  + 8 * 320 * 12;    // per warp [8][36]
    float* msk = qsm + 8 * 8 * 36;      // [320]  precomputed INF*(mask-1)

    int i = blockIdx.x, h = blockIdx.y;
    int tid = threadIdx.x, lane = tid & 31, w = tid >> 5;

    size_t base = ((size_t)i * NH + h) * (NRES * DH);
    const float* kg = g_k    + base;
    const float* qg = g_q    + base;
    const float* vg = g_v    + base;
    const float* gg = g_gate + base;

    for (int idx = tid; idx < NRES * 8; idx += 256) {
        int kk = idx >> 3, d4 = (idx & 7) * 4;
        *(float4*)&ks[kk * 36 + d4] = *(const float4*)&kg[kk * DH + d4];
        *(float4*)&vs[kk * 36 + d4] = *(const float4*)&vg[kk * DH + d4];
    }
    for (int idx = tid; idx < NRES; idx += 256)
        msk[idx] = 1.0e9f * (mask[(size_t)i * NRES + idx] - 1.f);
    __syncthreads();

    const float* bias_h = g_bias + (size_t)h * NN;
    float* am_w = am  + w * 320 * 12;
    float* q_w  = qsm + w * 8 * 36;

    for (int p = 0; p < 5; p++) {
        int qbase = p * 64 + w * 8;

        #pragma unroll
        for (int q = 0; q < 8; q++)
            q_w[q * 36 + lane] = qg[(qbase + q) * DH + lane];
        __syncwarp();

        // ---- scores: lane owns kj = lane + 32*j ----
        float s[8][10];
        #pragma unroll
        for (int q = 0; q < 8; q++)
            #pragma unroll
            for (int j = 0; j < 10; j++) s[q][j] = 0.f;

        for (int dc = 0; dc < 8; dc++) {
            float4 qv[8];
            #pragma unroll
            for (int q = 0; q < 8; q++)
                qv[q] = *(const float4*)&q_w[q * 36 + dc * 4];
            #pragma unroll
            for (int j = 0; j < 10; j++) {
                float4 kv = *(const float4*)&ks[(lane + 32 * j) * 36 + dc * 4];
                #pragma unroll
                for (int q = 0; q < 8; q++)
                    s[q][j] += qv[q].x * kv.x + qv[q].y * kv.y
                             + qv[q].z * kv.z + qv[q].w * kv.w;
            }
        }

        // ---- mask + triangle bias ----
        #pragma unroll
        for (int j = 0; j < 10; j++) {
            int kj = lane + 32 * j;
            float mb = msk[kj];
            #pragma unroll
            for (int q = 0; q < 8; q++)
                s[q][j] += mb + __ldg(&bias_h[(size_t)(qbase + q) * NRES + kj]);
        }

        // ---- softmax over full row (warp-wide) ----
        #pragma unroll
        for (int q = 0; q < 8; q++) {
            float m = s[q][0];
            #pragma unroll
            for (int j = 1; j < 10; j++) m = fmaxf(m, s[q][j]);
            #pragma unroll
            for (int off = 16; off >= 1; off >>= 1)
                m = fmaxf(m, __shfl_xor_sync(0xffffffffu, m, off));
            float ssum = 0.f;
            #pragma unroll
            for (int j = 0; j < 10; j++) { float e = __expf(s[q][j] - m); s[q][j] = e; ssum += e; }
            #pragma unroll
            for (int off = 16; off >= 1; off >>= 1)
                ssum += __shfl_xor_sync(0xffffffffu, ssum, off);
            float inv = 1.f / ssum;
            #pragma unroll
            for (int j = 0; j < 10; j++) s[q][j] *= inv;
        }

        // ---- stage a as [kk][q] for the o-phase ----
        #pragma unroll
        for (int j = 0; j < 10; j++) {
            int kj = lane + 32 * j;
            #pragma unroll
            for (int q = 0; q < 8; q++)
                am_w[kj * 12 + q] = s[q][j];
        }
        __syncwarp();

        // ---- o = a @ v : lane = d ----
        float o[8] = {0.f,0.f,0.f,0.f,0.f,0.f,0.f,0.f};
        #pragma unroll 4
        for (int kk = 0; kk < NRES; kk++) {
            float4 aA = *(const float4*)&am_w[kk * 12];
            float4 aB = *(const float4*)&am_w[kk * 12 + 4];
            float vv = vs[kk * 36 + lane];
            o[0] += aA.x * vv; o[1] += aA.y * vv; o[2] += aA.z * vv; o[3] += aA.w * vv;
            o[4] += aB.x * vv; o[5] += aB.y * vv; o[6] += aB.z * vv; o[7] += aB.w * vv;
        }

        // ---- gate + store ----
        #pragma unroll
        for (int q = 0; q < 8; q++) {
            float gate = gg[(qbase + q) * DH + lane];
            g_og[((size_t)i * NRES + (qbase + q)) * CDIM + h * DH + lane] = o[q] * gate;
        }
        __syncwarp();
    }
}

// =====================================================================
// Kernel C: output projection  out = og @ wo + bo
// =====================================================================
__global__ __launch_bounds__(256, 1) void kC(
    const float* __restrict__ wo, const float* __restrict__ bo,
    float* __restrict__ out)
{
    __shared__ float oT[CDIM*36];
    int tid = threadIdx.x;
    int Rb = blockIdx.x * 32;

    for (int idx = tid; idx < 32 * CDIM; idx += 256) {
        int r = idx >> 7, c = idx & 127;
        oT[c * 36 + r] = g_og[(size_t)(Rb + r) * CDIM + c];
    }
    __syncthreads();

    int tx = tid & 31, ty = tid >> 5;
    int col4 = tx * 4, row4 = ty * 4;
    float acc[4][4] = {};
    #pragma unroll 4
    for (int kk = 0; kk < CDIM; kk++) {
        float4 a = *(const float4*)&oT[kk * 36 + row4];
        float4 b = *(const float4*)&wo[kk * CDIM + col4];
        float av[4] = {a.x, a.y, a.z, a.w};
        float bv[4] = {b.x, b.y, b.z, b.w};
        #pragma unroll
        for (int r = 0; r < 4; r++)
            #pragma unroll
            for (int c = 0; c < 4; c++)
                acc[r][c] += av[r] * bv[c];
    }
    float4 bb = *(const float4*)&bo[col4];
    #pragma unroll
    for (int r = 0; r < 4; r++) {
        float4 o4 = make_float4(acc[r][0] + bb.x, acc[r][1] + bb.y,
                                acc[r][2] + bb.z, acc[r][3] + bb.w);
        *(float4*)&out[(size_t)(Rb + row4 + r) * CDIM + col4] = o4;
    }
}

// =====================================================================
extern "C" void kernel_launch(void* const* d_in, const int* in_sizes, int n_in,
                              void* d_out, int out_size)
{
    const float* x    = (const float*)d_in[0];
    const float* mask = (const float*)d_in[1];
    const float* lng  = (const float*)d_in[2];
    const float* lnb  = (const float*)d_in[3];
    const float* wb   = (const float*)d_in[4];
    const float* wq   = (const float*)d_in[5];
    const float* wk   = (const float*)d_in[6];
    const float* wv   = (const float*)d_in[7];
    const float* wg   = (const float*)d_in[8];
    const float* bg   = (const float*)d_in[9];
    const float* wo   = (const float*)d_in[10];
    const float* bo   = (const float*)d_in[11];
    float* out = (float*)d_out;

    cudaFuncSetAttribute(kB, cudaFuncAttributeMaxDynamicSharedMemorySize, SMEM_B);

    kA<<<NN / 32, 256>>>(x, lng, lnb, wb, wq, wk, wv, wg, bg);
    kB<<<dim3(NRES, NH), 256, SMEM_B>>>(mask);
    kC<<<NN / 32, 256>>>(wo, bo, out);
}

// round 2
// speedup vs baseline: 1.0776x; 1.0776x over previous
#include <cuda_runtime.h>
#include <cstdint>

#define NRES 320
#define CDIM 128
#define NH 4
#define DH 32
#define NN (NRES*NRES)

typedef unsigned long long u64;

// ---------- f32x2 helpers ----------
__device__ __forceinline__ void fma2(u64& d, u64 a, u64 b) {
    asm("fma.rn.f32x2 %0, %1, %2, %0;" : "+l"(d) : "l"(a), "l"(b));
}
__device__ __forceinline__ u64 pk(float x, float y) {
    u64 r; asm("mov.b64 %0, {%1,%2};" : "=l"(r) : "f"(x), "f"(y)); return r;
}
__device__ __forceinline__ float2 up(u64 v) {
    float2 r; asm("mov.b64 {%0,%1}, %2;" : "=f"(r.x), "=f"(r.y) : "l"(v)); return r;
}
__device__ __forceinline__ uint32_t s2u(const void* p) {
    return (uint32_t)__cvta_generic_to_shared(p);
}
// 16B shared load as two packed f32x2
__device__ __forceinline__ void lds2(u64& a, u64& b, uint32_t addr) {
    asm volatile("ld.shared.v2.u64 {%0,%1}, [%2];" : "=l"(a), "=l"(b) : "r"(addr));
}

// -------- device scratch --------
__device__ float g_q   [(size_t)NRES*NH*NRES*DH];   // [i][h][j][d]
__device__ float g_k   [(size_t)NRES*NH*NRES*DH];
__device__ float g_v   [(size_t)NRES*NH*NRES*DH];
__device__ float g_gate[(size_t)NRES*NH*NRES*DH];   // sigmoid applied
__device__ float g_og  [(size_t)NN*CDIM];
__device__ float g_bias[(size_t)NH*NN];             // [h][i][j]

// =====================================================================
// Kernel A: layernorm + q/k/v/gate projections + triangle bias
// 64 rows per block, 256 threads, 8x4 thread tiles, f32x2 math
// =====================================================================
__global__ __launch_bounds__(256, 2) void kA(
    const float* __restrict__ x,   const float* __restrict__ lng,
    const float* __restrict__ lnb, const float* __restrict__ wb,
    const float* __restrict__ wq,  const float* __restrict__ wk,
    const float* __restrict__ wv,  const float* __restrict__ wg,
    const float* __restrict__ bg)
{
    __shared__ float xsT[CDIM*68];     // [c][row], stride 68
    __shared__ float sg[CDIM], sb[CDIM];
    __shared__ float wbs[CDIM*NH];

    int tid = threadIdx.x;
    int Rb  = blockIdx.x * 64;

    if (tid < CDIM) { sg[tid] = lng[tid]; sb[tid] = lnb[tid]; }
    for (int idx = tid; idx < CDIM*NH; idx += 256) wbs[idx] = wb[idx];

    // ---- layernorm: 4 threads per row ----
    int row = tid >> 2, sub = tid & 3;
    float xv[32];
    const float* xr = x + (size_t)(Rb + row) * CDIM + sub * 32;
    #pragma unroll
    for (int m4 = 0; m4 < 8; m4++) {
        float4 t = *(const float4*)(xr + m4 * 4);
        xv[m4*4+0] = t.x; xv[m4*4+1] = t.y; xv[m4*4+2] = t.z; xv[m4*4+3] = t.w;
    }
    float sum = 0.f, sq = 0.f;
    #pragma unroll
    for (int m = 0; m < 32; m++) { sum += xv[m]; sq += xv[m]*xv[m]; }
    sum += __shfl_xor_sync(0xffffffffu, sum, 1, 4);
    sq  += __shfl_xor_sync(0xffffffffu, sq,  1, 4);
    sum += __shfl_xor_sync(0xffffffffu, sum, 2, 4);
    sq  += __shfl_xor_sync(0xffffffffu, sq,  2, 4);
    float mu = sum * (1.f / CDIM);
    float rs = rsqrtf(sq * (1.f / CDIM) - mu * mu + 1e-5f);

    __syncthreads();
    #pragma unroll
    for (int m = 0; m < 32; m++) {
        int c = sub * 32 + m;
        xsT[c * 68 + row] = (xv[m] - mu) * rs * sg[c] + sb[c];
    }
    __syncthreads();

    // ---- projections: 64x128 tile, thread tile 8 rows x 4 cols ----
    int tx = tid & 31, ty = tid >> 5;
    int col4 = tx * 4, row8 = ty * 8;
    int hh = col4 >> 5, dd = col4 & 31;
    uint32_t xsT_a = s2u(xsT) + row8 * 4;

    #pragma unroll 1
    for (int s = 0; s < 4; s++) {
        const float* W = (s == 0) ? wq : (s == 1) ? wk : (s == 2) ? wv : wg;
        u64 acc[4][4];
        #pragma unroll
        for (int r = 0; r < 4; r++)
            #pragma unroll
            for (int c = 0; c < 4; c++) acc[r][c] = 0ull;

        #pragma unroll 4
        for (int kk = 0; kk < CDIM; kk++) {
            u64 av[4];
            lds2(av[0], av[1], xsT_a + kk * 272);
            lds2(av[2], av[3], xsT_a + kk * 272 + 16);
            float4 b = __ldg((const float4*)&W[kk * CDIM + col4]);
            u64 bd[4] = { pk(b.x,b.x), pk(b.y,b.y), pk(b.z,b.z), pk(b.w,b.w) };
            #pragma unroll
            for (int r = 0; r < 4; r++)
                #pragma unroll
                for (int c = 0; c < 4; c++)
                    fma2(acc[r][c], av[r], bd[c]);
        }

        float o[8][4];
        #pragma unroll
        for (int r = 0; r < 4; r++)
            #pragma unroll
            for (int c = 0; c < 4; c++) {
                float2 t = up(acc[r][c]);
                o[2*r][c] = t.x; o[2*r+1][c] = t.y;
            }
        if (s == 0) {
            #pragma unroll
            for (int r = 0; r < 8; r++)
                #pragma unroll
                for (int c = 0; c < 4; c++) o[r][c] *= 0.17677669529663687f;
        }
        if (s == 3) {
            float4 bgv = *(const float4*)&bg[col4];
            float bvv[4] = {bgv.x, bgv.y, bgv.z, bgv.w};
            #pragma unroll
            for (int r = 0; r < 8; r++)
                #pragma unroll
                for (int c = 0; c < 4; c++)
                    o[r][c] = 1.f / (1.f + __expf(-(o[r][c] + bvv[c])));
        }
        float* dst = (s == 0) ? g_q : (s == 1) ? g_k : (s == 2) ? g_v : g_gate;
        #pragma unroll
        for (int r = 0; r < 8; r++) {
            int R = Rb + row8 + r;
            int i = R / NRES, j = R - i * NRES;
            *(float4*)&dst[(((size_t)i * NH + hh) * NRES + j) * DH + dd] =
                make_float4(o[r][0], o[r][1], o[r][2], o[r][3]);
        }
    }

    // ---- triangle bias: 64 rows x 4 heads ----
    {
        int r = tid >> 2, h2 = tid & 3;
        float acc = 0.f;
        #pragma unroll 8
        for (int kk = 0; kk < CDIM; kk++)
            acc += xsT[kk * 68 + r] * wbs[kk * NH + h2];
        g_bias[(size_t)h2 * NN + Rb + r] = acc;
    }
}

// =====================================================================
// Kernel B: attention per (i,h). 256 threads, 8 warps, 8 q/warp/pass
// =====================================================================
#define SMEM_B ((320*36*2 + 8*320*12 + 8*8*36 + 320) * 4)

__global__ __launch_bounds__(256, 1) void kB(const float* __restrict__ mask)
{
    extern __shared__ float sm[];
    float* ks  = sm;                    // [320][36]
    float* vs  = ks  + 320 * 36;        // [320][36]
    float* am  = vs  + 320 * 36;        // per warp [320][12]
    float* qsm = am  + 8 * 320 * 12;    // per warp [8][36]
    float* msk = qsm + 8 * 8 * 36;      // [320]

    int i = blockIdx.x, h = blockIdx.y;
    int tid = threadIdx.x, lane = tid & 31, w = tid >> 5;

    size_t base = ((size_t)i * NH + h) * (NRES * DH);
    const float* kg = g_k    + base;
    const float* qg = g_q    + base;
    const float* vg = g_v    + base;
    const float* gg = g_gate + base;

    for (int idx = tid; idx < NRES * 8; idx += 256) {
        int kk = idx >> 3, d4 = (idx & 7) * 4;
        *(float4*)&ks[kk * 36 + d4] = *(const float4*)&kg[kk * DH + d4];
        *(float4*)&vs[kk * 36 + d4] = *(const float4*)&vg[kk * DH + d4];
    }
    for (int idx = tid; idx < NRES; idx += 256)
        msk[idx] = 1.0e9f * (mask[(size_t)i * NRES + idx] - 1.f);
    __syncthreads();

    const float* bias_h = g_bias + (size_t)h * NN;
    float* am_w = am  + w * 320 * 12;
    float* q_w  = qsm + w * 8 * 36;

    uint32_t ks_a = s2u(ks);
    uint32_t vs_a = s2u(vs);
    uint32_t am_a = s2u(am_w);
    uint32_t qw_a = s2u(q_w);

    for (int p = 0; p < 5; p++) {
        int qbase = p * 64 + w * 8;

        #pragma unroll
        for (int q = 0; q < 8; q++)
            q_w[q * 36 + lane] = qg[(qbase + q) * DH + lane];
        __syncwarp();

        // ---- scores in f32x2 (d-pairs), j processed in two halves of 5 ----
        float s[8][10];
        #pragma unroll 1
        for (int h2 = 0; h2 < 2; h2++) {
            u64 s2[8][5];
            #pragma unroll
            for (int q = 0; q < 8; q++)
                #pragma unroll
                for (int jj = 0; jj < 5; jj++) s2[q][jj] = 0ull;

            #pragma unroll 2
            for (int dc = 0; dc < 8; dc++) {
                u64 qp[8][2];
                #pragma unroll
                for (int q = 0; q < 8; q++)
                    lds2(qp[q][0], qp[q][1], qw_a + q * 144 + dc * 16);
                #pragma unroll
                for (int jj = 0; jj < 5; jj++) {
                    int kj = lane + 32 * (h2 * 5 + jj);
                    u64 k0, k1;
                    lds2(k0, k1, ks_a + kj * 144 + dc * 16);
                    #pragma unroll
                    for (int q = 0; q < 8; q++) {
                        fma2(s2[q][jj], qp[q][0], k0);
                        fma2(s2[q][jj], qp[q][1], k1);
                    }
                }
            }
            #pragma unroll
            for (int q = 0; q < 8; q++)
                #pragma unroll
                for (int jj = 0; jj < 5; jj++) {
                    float2 t = up(s2[q][jj]);
                    s[q][h2 * 5 + jj] = t.x + t.y;
                }
        }

        // ---- mask + triangle bias ----
        #pragma unroll
        for (int j = 0; j < 10; j++) {
            int kj = lane + 32 * j;
            float mb = msk[kj];
            #pragma unroll
            for (int q = 0; q < 8; q++)
                s[q][j] += mb + __ldg(&bias_h[(size_t)(qbase + q) * NRES + kj]);
        }

        // ---- softmax (warp-wide over 320) ----
        #pragma unroll
        for (int q = 0; q < 8; q++) {
            float m = s[q][0];
            #pragma unroll
            for (int j = 1; j < 10; j++) m = fmaxf(m, s[q][j]);
            #pragma unroll
            for (int off = 16; off >= 1; off >>= 1)
                m = fmaxf(m, __shfl_xor_sync(0xffffffffu, m, off));
            float ssum = 0.f;
            #pragma unroll
            for (int j = 0; j < 10; j++) { float e = __expf(s[q][j] - m); s[q][j] = e; ssum += e; }
            #pragma unroll
            for (int off = 16; off >= 1; off >>= 1)
                ssum += __shfl_xor_sync(0xffffffffu, ssum, off);
            float inv = 1.f / ssum;
            #pragma unroll
            for (int j = 0; j < 10; j++) s[q][j] *= inv;
        }

        // ---- stage a as [kk][q] (two STS.128 per j) ----
        #pragma unroll
        for (int j = 0; j < 10; j++) {
            int kj = lane + 32 * j;
            *(float4*)&am_w[kj * 12]     = make_float4(s[0][j], s[1][j], s[2][j], s[3][j]);
            *(float4*)&am_w[kj * 12 + 4] = make_float4(s[4][j], s[5][j], s[6][j], s[7][j]);
        }
        __syncwarp();

        // ---- o = a @ v in f32x2 (q-pairs); lane = d ----
        u64 o2[4] = {0ull, 0ull, 0ull, 0ull};
        #pragma unroll 4
        for (int kk = 0; kk < NRES; kk++) {
            u64 a01, a23, a45, a67;
            lds2(a01, a23, am_a + kk * 48);
            lds2(a45, a67, am_a + kk * 48 + 16);
            float vv = vs[kk * 36 + lane];
            u64 vd = pk(vv, vv);
            fma2(o2[0], a01, vd);
            fma2(o2[1], a23, vd);
            fma2(o2[2], a45, vd);
            fma2(o2[3], a67, vd);
        }

        // ---- gate + store ----
        float oo[8];
        #pragma unroll
        for (int q2 = 0; q2 < 4; q2++) {
            float2 t = up(o2[q2]);
            oo[2*q2] = t.x; oo[2*q2+1] = t.y;
        }
        #pragma unroll
        for (int q = 0; q < 8; q++) {
            float gate = gg[(qbase + q) * DH + lane];
            g_og[((size_t)i * NRES + (qbase + q)) * CDIM + h * DH + lane] = oo[q] * gate;
        }
        __syncwarp();
    }
}

// =====================================================================
// Kernel C: output projection  out = og @ wo + bo   (f32x2, 64-row tiles)
// =====================================================================
__global__ __launch_bounds__(256, 2) void kC(
    const float* __restrict__ wo, const float* __restrict__ bo,
    float* __restrict__ out)
{
    __shared__ float oT[CDIM*68];
    int tid = threadIdx.x;
    int Rb = blockIdx.x * 64;

    for (int idx = tid; idx < 64 * CDIM; idx += 256) {
        int r = idx >> 7, c = idx & 127;
        oT[c * 68 + r] = g_og[(size_t)(Rb + r) * CDIM + c];
    }
    __syncthreads();

    int tx = tid & 31, ty = tid >> 5;
    int col4 = tx * 4, row8 = ty * 8;
    uint32_t oT_a = s2u(oT) + row8 * 4;

    u64 acc[4][4];
    #pragma unroll
    for (int r = 0; r < 4; r++)
        #pragma unroll
        for (int c = 0; c < 4; c++) acc[r][c] = 0ull;

    #pragma unroll 4
    for (int kk = 0; kk < CDIM; kk++) {
        u64 av[4];
        lds2(av[0], av[1], oT_a + kk * 272);
        lds2(av[2], av[3], oT_a + kk * 272 + 16);
        float4 b = __ldg((const float4*)&wo[kk * CDIM + col4]);
        u64 bd[4] = { pk(b.x,b.x), pk(b.y,b.y), pk(b.z,b.z), pk(b.w,b.w) };
        #pragma unroll
        for (int r = 0; r < 4; r++)
            #pragma unroll
            for (int c = 0; c < 4; c++)
                fma2(acc[r][c], av[r], bd[c]);
    }

    float4 bb = *(const float4*)&bo[col4];
    float bvv[4] = {bb.x, bb.y, bb.z, bb.w};
    #pragma unroll
    for (int r = 0; r < 4; r++) {
        float2 t0 = up(acc[r][0]), t1 = up(acc[r][1]), t2 = up(acc[r][2]), t3 = up(acc[r][3]);
        *(float4*)&out[(size_t)(Rb + row8 + 2*r) * CDIM + col4] =
            make_float4(t0.x + bvv[0], t1.x + bvv[1], t2.x + bvv[2], t3.x + bvv[3]);
        *(float4*)&out[(size_t)(Rb + row8 + 2*r + 1) * CDIM + col4] =
            make_float4(t0.y + bvv[0], t1.y + bvv[1], t2.y + bvv[2], t3.y + bvv[3]);
    }
}

// =====================================================================
extern "C" void kernel_launch(void* const* d_in, const int* in_sizes, int n_in,
                              void* d_out, int out_size)
{
    const float* x    = (const float*)d_in[0];
    const float* mask = (const float*)d_in[1];
    const float* lng  = (const float*)d_in[2];
    const float* lnb  = (const float*)d_in[3];
    const float* wb   = (const float*)d_in[4];
    const float* wq   = (const float*)d_in[5];
    const float* wk   = (const float*)d_in[6];
    const float* wv   = (const float*)d_in[7];
    const float* wg   = (const float*)d_in[8];
    const float* bg   = (const float*)d_in[9];
    const float* wo   = (const float*)d_in[10];
    const float* bo   = (const float*)d_in[11];
    float* out = (float*)d_out;

    cudaFuncSetAttribute(kB, cudaFuncAttributeMaxDynamicSharedMemorySize, SMEM_B);

    kA<<<NN / 64, 256>>>(x, lng, lnb, wb, wq, wk, wv, wg, bg);
    kB<<<dim3(NRES, NH), 256, SMEM_B>>>(mask);
    kC<<<NN / 64, 256>>>(wo, bo, out);
}

// round 4
// speedup vs baseline: 1.0812x; 1.0034x over previous
#include <cuda_runtime.h>
#include <cstdint>

#define NRES 320
#define CDIM 128
#define NH 4
#define DH 32
#define NN (NRES*NRES)

typedef unsigned long long u64;

// ---------- f32x2 helpers ----------
__device__ __forceinline__ void fma2(u64& d, u64 a, u64 b) {
    asm("fma.rn.f32x2 %0, %1, %2, %0;" : "+l"(d) : "l"(a), "l"(b));
}
__device__ __forceinline__ u64 pk(float x, float y) {
    u64 r; asm("mov.b64 %0, {%1,%2};" : "=l"(r) : "f"(x), "f"(y)); return r;
}
__device__ __forceinline__ float2 up(u64 v) {
    float2 r; asm("mov.b64 {%0,%1}, %2;" : "=f"(r.x), "=f"(r.y) : "l"(v)); return r;
}
__device__ __forceinline__ uint32_t s2u(const void* p) {
    return (uint32_t)__cvta_generic_to_shared(p);
}
__device__ __forceinline__ void lds2(u64& a, u64& b, uint32_t addr) {
    asm volatile("ld.shared.v2.u64 {%0,%1}, [%2];" : "=l"(a), "=l"(b) : "r"(addr));
}

// -------- device scratch --------
__device__ float g_q   [(size_t)NRES*NH*NRES*DH];   // [i][h][j][d]
__device__ float g_k   [(size_t)NRES*NH*NRES*DH];
__device__ float g_v   [(size_t)NRES*NH*NRES*DH];
__device__ float g_gate[(size_t)NRES*NH*NRES*DH];
__device__ float g_og  [(size_t)NN*CDIM];
__device__ float g_bias[(size_t)NH*NN];             // [h][i][j]

// =====================================================================
// Kernel A: layernorm + q/k/v/gate projections + triangle bias
// (unchanged — 342us, protect)
// =====================================================================
__global__ __launch_bounds__(256, 2) void kA(
    const float* __restrict__ x,   const float* __restrict__ lng,
    const float* __restrict__ lnb, const float* __restrict__ wb,
    const float* __restrict__ wq,  const float* __restrict__ wk,
    const float* __restrict__ wv,  const float* __restrict__ wg,
    const float* __restrict__ bg)
{
    __shared__ float xsT[CDIM*68];
    __shared__ float sg[CDIM], sb[CDIM];
    __shared__ float wbs[CDIM*NH];

    int tid = threadIdx.x;
    int Rb  = blockIdx.x * 64;

    if (tid < CDIM) { sg[tid] = lng[tid]; sb[tid] = lnb[tid]; }
    for (int idx = tid; idx < CDIM*NH; idx += 256) wbs[idx] = wb[idx];

    int row = tid >> 2, sub = tid & 3;
    float xv[32];
    const float* xr = x + (size_t)(Rb + row) * CDIM + sub * 32;
    #pragma unroll
    for (int m4 = 0; m4 < 8; m4++) {
        float4 t = *(const float4*)(xr + m4 * 4);
        xv[m4*4+0] = t.x; xv[m4*4+1] = t.y; xv[m4*4+2] = t.z; xv[m4*4+3] = t.w;
    }
    float sum = 0.f, sq = 0.f;
    #pragma unroll
    for (int m = 0; m < 32; m++) { sum += xv[m]; sq += xv[m]*xv[m]; }
    sum += __shfl_xor_sync(0xffffffffu, sum, 1, 4);
    sq  += __shfl_xor_sync(0xffffffffu, sq,  1, 4);
    sum += __shfl_xor_sync(0xffffffffu, sum, 2, 4);
    sq  += __shfl_xor_sync(0xffffffffu, sq,  2, 4);
    float mu = sum * (1.f / CDIM);
    float rs = rsqrtf(sq * (1.f / CDIM) - mu * mu + 1e-5f);

    __syncthreads();
    #pragma unroll
    for (int m = 0; m < 32; m++) {
        int c = sub * 32 + m;
        xsT[c * 68 + row] = (xv[m] - mu) * rs * sg[c] + sb[c];
    }
    __syncthreads();

    int tx = tid & 31, ty = tid >> 5;
    int col4 = tx * 4, row8 = ty * 8;
    int hh = col4 >> 5, dd = col4 & 31;
    uint32_t xsT_a = s2u(xsT) + row8 * 4;

    #pragma unroll 1
    for (int s = 0; s < 4; s++) {
        const float* W = (s == 0) ? wq : (s == 1) ? wk : (s == 2) ? wv : wg;
        u64 acc[4][4];
        #pragma unroll
        for (int r = 0; r < 4; r++)
            #pragma unroll
            for (int c = 0; c < 4; c++) acc[r][c] = 0ull;

        #pragma unroll 4
        for (int kk = 0; kk < CDIM; kk++) {
            u64 av[4];
            lds2(av[0], av[1], xsT_a + kk * 272);
            lds2(av[2], av[3], xsT_a + kk * 272 + 16);
            float4 b = __ldg((const float4*)&W[kk * CDIM + col4]);
            u64 bd[4] = { pk(b.x,b.x), pk(b.y,b.y), pk(b.z,b.z), pk(b.w,b.w) };
            #pragma unroll
            for (int r = 0; r < 4; r++)
                #pragma unroll
                for (int c = 0; c < 4; c++)
                    fma2(acc[r][c], av[r], bd[c]);
        }

        float o[8][4];
        #pragma unroll
        for (int r = 0; r < 4; r++)
            #pragma unroll
            for (int c = 0; c < 4; c++) {
                float2 t = up(acc[r][c]);
                o[2*r][c] = t.x; o[2*r+1][c] = t.y;
            }
        if (s == 0) {
            #pragma unroll
            for (int r = 0; r < 8; r++)
                #pragma unroll
                for (int c = 0; c < 4; c++) o[r][c] *= 0.17677669529663687f;
        }
        if (s == 3) {
            float4 bgv = *(const float4*)&bg[col4];
            float bvv[4] = {bgv.x, bgv.y, bgv.z, bgv.w};
            #pragma unroll
            for (int r = 0; r < 8; r++)
                #pragma unroll
                for (int c = 0; c < 4; c++)
                    o[r][c] = 1.f / (1.f + __expf(-(o[r][c] + bvv[c])));
        }
        float* dst = (s == 0) ? g_q : (s == 1) ? g_k : (s == 2) ? g_v : g_gate;
        #pragma unroll
        for (int r = 0; r < 8; r++) {
            int R = Rb + row8 + r;
            int i = R / NRES, j = R - i * NRES;
            *(float4*)&dst[(((size_t)i * NH + hh) * NRES + j) * DH + dd] =
                make_float4(o[r][0], o[r][1], o[r][2], o[r][3]);
        }
    }

    {
        int r = tid >> 2, h2 = tid & 3;
        float acc = 0.f;
        #pragma unroll 8
        for (int kk = 0; kk < CDIM; kk++)
            acc += xsT[kk * 68 + r] * wbs[kk * NH + h2];
        g_bias[(size_t)h2 * NN + Rb + r] = acc;
    }
}

// =====================================================================
// Kernel B: attention per (i,h). 512 threads = 16 warps = 8 pairs.
// Each warp: 8 queries x 160-kj half. am stride = 8 floats (32B, aligned).
// =====================================================================
#define KS_OFF   0
#define VS_OFF   (320*36)
#define AM_OFF   (VS_OFF + 320*36)            // 16 warps x [160][8]
#define QS_OFF   (AM_OFF + 16*160*8)          // 8 pairs x [8][32]
#define MSK_OFF  (QS_OFF + 8*8*32)
#define RED_OFF  (MSK_OFF + 320)              // 16 warps x 8 q x {m,s}
#define OP_OFF   (RED_OFF + 16*8*2)           // 8 pairs x [8][32]
#define SMEM_B   ((OP_OFF + 8*8*32) * 4)

__global__ __launch_bounds__(512, 1) void kB(const float* __restrict__ mask)
{
    extern __shared__ float sm[];
    float* ks    = sm + KS_OFF;
    float* vs    = sm + VS_OFF;
    float* am    = sm + AM_OFF;
    float* qsm   = sm + QS_OFF;
    float* msk   = sm + MSK_OFF;
    float* red   = sm + RED_OFF;
    float* opart = sm + OP_OFF;

    int i = blockIdx.x, h = blockIdx.y;
    int tid = threadIdx.x, lane = tid & 31, w = tid >> 5;
    int p2 = w >> 1, half = w & 1;
    int khalf = half * 160;

    size_t base = ((size_t)i * NH + h) * (NRES * DH);
    const float* kg = g_k    + base;
    const float* qg = g_q    + base;
    const float* vg = g_v    + base;
    const float* gg = g_gate + base;

    for (int idx = tid; idx < NRES * 8; idx += 512) {
        int kk = idx >> 3, d4 = (idx & 7) * 4;
        *(float4*)&ks[kk * 36 + d4] = *(const float4*)&kg[kk * DH + d4];
        *(float4*)&vs[kk * 36 + d4] = *(const float4*)&vg[kk * DH + d4];
    }
    for (int idx = tid; idx < NRES; idx += 512)
        msk[idx] = 1.0e9f * (mask[(size_t)i * NRES + idx] - 1.f);

    const float* bias_h = g_bias + (size_t)h * NN;
    float* am_w = am + w * 160 * 8;
    float* q_p  = qsm + p2 * 8 * 32;

    uint32_t ks_a = s2u(ks) + khalf * 144;
    uint32_t am_a = s2u(am_w);
    uint32_t qp_a = s2u(q_p);

    __syncthreads();

    #pragma unroll 1
    for (int p = 0; p < 5; p++) {
        int qbase = p * 64 + p2 * 8;

        // ---- stage q (one warp of the pair writes) ----
        if (!half) {
            #pragma unroll
            for (int q = 0; q < 8; q++)
                q_p[q * 32 + lane] = qg[(qbase + q) * DH + lane];
        }
        __syncthreads();

        // ---- scores over this warp's 160 kj, f32x2 d-pairs ----
        u64 s2[8][5];
        #pragma unroll
        for (int q = 0; q < 8; q++)
            #pragma unroll
            for (int jj = 0; jj < 5; jj++) s2[q][jj] = 0ull;

        #pragma unroll 2
        for (int dc = 0; dc < 8; dc++) {
            u64 kv2[5][2];
            #pragma unroll
            for (int jj = 0; jj < 5; jj++)
                lds2(kv2[jj][0], kv2[jj][1], ks_a + (32*jj + lane) * 144 + dc * 16);
            #pragma unroll
            for (int q = 0; q < 8; q++) {
                u64 q0, q1;
                lds2(q0, q1, qp_a + q * 128 + dc * 16);
                #pragma unroll
                for (int jj = 0; jj < 5; jj++) {
                    fma2(s2[q][jj], q0, kv2[jj][0]);
                    fma2(s2[q][jj], q1, kv2[jj][1]);
                }
            }
        }

        // ---- fold + mask + bias ----
        float s[8][5];
        #pragma unroll
        for (int jj = 0; jj < 5; jj++) {
            int kj = khalf + 32*jj + lane;
            float mb = msk[kj];
            #pragma unroll
            for (int q = 0; q < 8; q++) {
                float2 t = up(s2[q][jj]);
                s[q][jj] = t.x + t.y + mb + __ldg(&bias_h[(size_t)(qbase + q) * NRES + kj]);
            }
        }

        // ---- local softmax stats over 160 ----
        float mloc[8], sloc[8];
        #pragma unroll
        for (int q = 0; q < 8; q++) {
            float m = s[q][0];
            #pragma unroll
            for (int jj = 1; jj < 5; jj++) m = fmaxf(m, s[q][jj]);
            #pragma unroll
            for (int off = 16; off >= 1; off >>= 1)
                m = fmaxf(m, __shfl_xor_sync(0xffffffffu, m, off));
            float ssum = 0.f;
            #pragma unroll
            for (int jj = 0; jj < 5; jj++) {
                float e = __expf(s[q][jj] - m); s[q][jj] = e; ssum += e;
            }
            #pragma unroll
            for (int off = 16; off >= 1; off >>= 1)
                ssum += __shfl_xor_sync(0xffffffffu, ssum, off);
            mloc[q] = m; sloc[q] = ssum;
            if (lane == q) {
                red[(w * 8 + q) * 2]     = m;
                red[(w * 8 + q) * 2 + 1] = ssum;
            }
        }
        __syncthreads();

        // ---- combine with other half, write a into am ----
        int wo = w ^ 1;
        #pragma unroll
        for (int q = 0; q < 8; q++) {
            float mo = red[(wo * 8 + q) * 2];
            float so = red[(wo * 8 + q) * 2 + 1];
            float M  = fmaxf(mloc[q], mo);
            float tot = sloc[q] * __expf(mloc[q] - M) + so * __expf(mo - M);
            float fac = __expf(mloc[q] - M) / tot;
            #pragma unroll
            for (int jj = 0; jj < 5; jj++) s[q][jj] *= fac;
        }
        #pragma unroll
        for (int jj = 0; jj < 5; jj++) {
            int kl = 32*jj + lane;
            *(float4*)&am_w[kl * 8]     = make_float4(s[0][jj], s[1][jj], s[2][jj], s[3][jj]);
            *(float4*)&am_w[kl * 8 + 4] = make_float4(s[4][jj], s[5][jj], s[6][jj], s[7][jj]);
        }
        __syncwarp();

        // ---- o over this warp's 160 kk ----
        u64 o2[4] = {0ull, 0ull, 0ull, 0ull};
        #pragma unroll 4
        for (int kl = 0; kl < 160; kl++) {
            u64 a01, a23, a45, a67;
            lds2(a01, a23, am_a + kl * 32);
            lds2(a45, a67, am_a + kl * 32 + 16);
            float vv = vs[(khalf + kl) * 36 + lane];
            u64 vd = pk(vv, vv);
            fma2(o2[0], a01, vd);
            fma2(o2[1], a23, vd);
            fma2(o2[2], a45, vd);
            fma2(o2[3], a67, vd);
        }
        float oo[8];
        #pragma unroll
        for (int q2 = 0; q2 < 4; q2++) {
            float2 t = up(o2[q2]);
            oo[2*q2] = t.x; oo[2*q2+1] = t.y;
        }

        // ---- pair merge + gate + store ----
        if (half) {
            #pragma unroll
            for (int q = 0; q < 8; q++)
                opart[(p2 * 8 + q) * 32 + lane] = oo[q];
        }
        __syncthreads();
        if (!half) {
            #pragma unroll
            for (int q = 0; q < 8; q++) {
                float o = oo[q] + opart[(p2 * 8 + q) * 32 + lane];
                float gate = gg[(qbase + q) * DH + lane];
                g_og[((size_t)i * NRES + (qbase + q)) * CDIM + h * DH + lane] = o * gate;
            }
        }
        __syncthreads();
    }
}

// =====================================================================
// Kernel C: output projection (unchanged)
// =====================================================================
__global__ __launch_bounds__(256, 2) void kC(
    const float* __restrict__ wo, const float* __restrict__ bo,
    float* __restrict__ out)
{
    __shared__ float oT[CDIM*68];
    int tid = threadIdx.x;
    int Rb = blockIdx.x * 64;

    for (int idx = tid; idx < 64 * CDIM; idx += 256) {
        int r = idx >> 7, c = idx & 127;
        oT[c * 68 + r] = g_og[(size_t)(Rb + r) * CDIM + c];
    }
    __syncthreads();

    int tx = tid & 31, ty = tid >> 5;
    int col4 = tx * 4, row8 = ty * 8;
    uint32_t oT_a = s2u(oT) + row8 * 4;

    u64 acc[4][4];
    #pragma unroll
    for (int r = 0; r < 4; r++)
        #pragma unroll
        for (int c = 0; c < 4; c++) acc[r][c] = 0ull;

    #pragma unroll 4
    for (int kk = 0; kk < CDIM; kk++) {
        u64 av[4];
        lds2(av[0], av[1], oT_a + kk * 272);
        lds2(av[2], av[3], oT_a + kk * 272 + 16);
        float4 b = __ldg((const float4*)&wo[kk * CDIM + col4]);
        u64 bd[4] = { pk(b.x,b.x), pk(b.y,b.y), pk(b.z,b.z), pk(b.w,b.w) };
        #pragma unroll
        for (int r = 0; r < 4; r++)
            #pragma unroll
            for (int c = 0; c < 4; c++)
                fma2(acc[r][c], av[r], bd[c]);
    }

    float4 bb = *(const float4*)&bo[col4];
    float bvv[4] = {bb.x, bb.y, bb.z, bb.w};
    #pragma unroll
    for (int r = 0; r < 4; r++) {
        float2 t0 = up(acc[r][0]), t1 = up(acc[r][1]), t2 = up(acc[r][2]), t3 = up(acc[r][3]);
        *(float4*)&out[(size_t)(Rb + row8 + 2*r) * CDIM + col4] =
            make_float4(t0.x + bvv[0], t1.x + bvv[1], t2.x + bvv[2], t3.x + bvv[3]);
        *(float4*)&out[(size_t)(Rb + row8 + 2*r + 1) * CDIM + col4] =
            make_float4(t0.y + bvv[0], t1.y + bvv[1], t2.y + bvv[2], t3.y + bvv[3]);
    }
}

// =====================================================================
extern "C" void kernel_launch(void* const* d_in, const int* in_sizes, int n_in,
                              void* d_out, int out_size)
{
    const float* x    = (const float*)d_in[0];
    const float* mask = (const float*)d_in[1];
    const float* lng  = (const float*)d_in[2];
    const float* lnb  = (const float*)d_in[3];
    const float* wb   = (const float*)d_in[4];
    const float* wq   = (const float*)d_in[5];
    const float* wk   = (const float*)d_in[6];
    const float* wv   = (const float*)d_in[7];
    const float* wg   = (const float*)d_in[8];
    const float* bg   = (const float*)d_in[9];
    const float* wo   = (const float*)d_in[10];
    const float* bo   = (const float*)d_in[11];
    float* out = (float*)d_out;

    cudaFuncSetAttribute(kB, cudaFuncAttributeMaxDynamicSharedMemorySize, SMEM_B);

    kA<<<NN / 64, 256>>>(x, lng, lnb, wb, wq, wk, wv, wg, bg);
    kB<<<dim3(NRES, NH), 512, SMEM_B>>>(mask);
    kC<<<NN / 64, 256>>>(wo, bo, out);
}

// round 5
// speedup vs baseline: 1.6129x; 1.4917x over previous
#include <cuda_runtime.h>
#include <cstdint>

#define NRES 320
#define CDIM 128
#define NH 4
#define DH 32
#define NN (NRES*NRES)

typedef unsigned long long u64;

// ---------- f32x2 helpers (kA/kC) ----------
__device__ __forceinline__ void fma2(u64& d, u64 a, u64 b) {
    asm("fma.rn.f32x2 %0, %1, %2, %0;" : "+l"(d) : "l"(a), "l"(b));
}
__device__ __forceinline__ u64 pk(float x, float y) {
    u64 r; asm("mov.b64 %0, {%1,%2};" : "=l"(r) : "f"(x), "f"(y)); return r;
}
__device__ __forceinline__ float2 up(u64 v) {
    float2 r; asm("mov.b64 {%0,%1}, %2;" : "=f"(r.x), "=f"(r.y) : "l"(v)); return r;
}
__device__ __forceinline__ uint32_t s2u(const void* p) {
    return (uint32_t)__cvta_generic_to_shared(p);
}
__device__ __forceinline__ void lds2(u64& a, u64& b, uint32_t addr) {
    asm volatile("ld.shared.v2.u64 {%0,%1}, [%2];" : "=l"(a), "=l"(b) : "r"(addr));
}

// ---------- tf32 mma helpers (kB) ----------
__device__ __forceinline__ uint32_t f2tf(float f) {
    uint32_t u; asm("cvt.rna.tf32.f32 %0, %1;" : "=r"(u) : "f"(f)); return u;
}
__device__ __forceinline__ void mma_tf32(float* d,
    uint32_t a0, uint32_t a1, uint32_t a2, uint32_t a3,
    uint32_t b0, uint32_t b1)
{
    asm volatile(
        "mma.sync.aligned.m16n8k8.row.col.f32.tf32.tf32.f32 "
        "{%0,%1,%2,%3}, {%4,%5,%6,%7}, {%8,%9}, {%0,%1,%2,%3};"
        : "+f"(d[0]), "+f"(d[1]), "+f"(d[2]), "+f"(d[3])
        : "r"(a0), "r"(a1), "r"(a2), "r"(a3), "r"(b0), "r"(b1));
}

// -------- device scratch --------
__device__ float g_q   [(size_t)NRES*NH*NRES*DH];   // [i][h][j][d]
__device__ float g_k   [(size_t)NRES*NH*NRES*DH];
__device__ float g_v   [(size_t)NRES*NH*NRES*DH];
__device__ float g_gate[(size_t)NRES*NH*NRES*DH];
__device__ float g_og  [(size_t)NN*CDIM];
__device__ float g_bias[(size_t)NH*NN];             // [h][q][j]

// =====================================================================
// Kernel A: layernorm + q/k/v/gate projections + triangle bias
// (unchanged — protect)
// =====================================================================
__global__ __launch_bounds__(256, 2) void kA(
    const float* __restrict__ x,   const float* __restrict__ lng,
    const float* __restrict__ lnb, const float* __restrict__ wb,
    const float* __restrict__ wq,  const float* __restrict__ wk,
    const float* __restrict__ wv,  const float* __restrict__ wg,
    const float* __restrict__ bg)
{
    __shared__ float xsT[CDIM*68];
    __shared__ float sg[CDIM], sb[CDIM];
    __shared__ float wbs[CDIM*NH];

    int tid = threadIdx.x;
    int Rb  = blockIdx.x * 64;

    if (tid < CDIM) { sg[tid] = lng[tid]; sb[tid] = lnb[tid]; }
    for (int idx = tid; idx < CDIM*NH; idx += 256) wbs[idx] = wb[idx];

    int row = tid >> 2, sub = tid & 3;
    float xv[32];
    const float* xr = x + (size_t)(Rb + row) * CDIM + sub * 32;
    #pragma unroll
    for (int m4 = 0; m4 < 8; m4++) {
        float4 t = *(const float4*)(xr + m4 * 4);
        xv[m4*4+0] = t.x; xv[m4*4+1] = t.y; xv[m4*4+2] = t.z; xv[m4*4+3] = t.w;
    }
    float sum = 0.f, sq = 0.f;
    #pragma unroll
    for (int m = 0; m < 32; m++) { sum += xv[m]; sq += xv[m]*xv[m]; }
    sum += __shfl_xor_sync(0xffffffffu, sum, 1, 4);
    sq  += __shfl_xor_sync(0xffffffffu, sq,  1, 4);
    sum += __shfl_xor_sync(0xffffffffu, sum, 2, 4);
    sq  += __shfl_xor_sync(0xffffffffu, sq,  2, 4);
    float mu = sum * (1.f / CDIM);
    float rs = rsqrtf(sq * (1.f / CDIM) - mu * mu + 1e-5f);

    __syncthreads();
    #pragma unroll
    for (int m = 0; m < 32; m++) {
        int c = sub * 32 + m;
        xsT[c * 68 + row] = (xv[m] - mu) * rs * sg[c] + sb[c];
    }
    __syncthreads();

    int tx = tid & 31, ty = tid >> 5;
    int col4 = tx * 4, row8 = ty * 8;
    int hh = col4 >> 5, dd = col4 & 31;
    uint32_t xsT_a = s2u(xsT) + row8 * 4;

    #pragma unroll 1
    for (int s = 0; s < 4; s++) {
        const float* W = (s == 0) ? wq : (s == 1) ? wk : (s == 2) ? wv : wg;
        u64 acc[4][4];
        #pragma unroll
        for (int r = 0; r < 4; r++)
            #pragma unroll
            for (int c = 0; c < 4; c++) acc[r][c] = 0ull;

        #pragma unroll 4
        for (int kk = 0; kk < CDIM; kk++) {
            u64 av[4];
            lds2(av[0], av[1], xsT_a + kk * 272);
            lds2(av[2], av[3], xsT_a + kk * 272 + 16);
            float4 b = __ldg((const float4*)&W[kk * CDIM + col4]);
            u64 bd[4] = { pk(b.x,b.x), pk(b.y,b.y), pk(b.z,b.z), pk(b.w,b.w) };
            #pragma unroll
            for (int r = 0; r < 4; r++)
                #pragma unroll
                for (int c = 0; c < 4; c++)
                    fma2(acc[r][c], av[r], bd[c]);
        }

        float o[8][4];
        #pragma unroll
        for (int r = 0; r < 4; r++)
            #pragma unroll
            for (int c = 0; c < 4; c++) {
                float2 t = up(acc[r][c]);
                o[2*r][c] = t.x; o[2*r+1][c] = t.y;
            }
        if (s == 0) {
            #pragma unroll
            for (int r = 0; r < 8; r++)
                #pragma unroll
                for (int c = 0; c < 4; c++) o[r][c] *= 0.17677669529663687f;
        }
        if (s == 3) {
            float4 bgv = *(const float4*)&bg[col4];
            float bvv[4] = {bgv.x, bgv.y, bgv.z, bgv.w};
            #pragma unroll
            for (int r = 0; r < 8; r++)
                #pragma unroll
                for (int c = 0; c < 4; c++)
                    o[r][c] = 1.f / (1.f + __expf(-(o[r][c] + bvv[c])));
        }
        float* dst = (s == 0) ? g_q : (s == 1) ? g_k : (s == 2) ? g_v : g_gate;
        #pragma unroll
        for (int r = 0; r < 8; r++) {
            int R = Rb + row8 + r;
            int i = R / NRES, j = R - i * NRES;
            *(float4*)&dst[(((size_t)i * NH + hh) * NRES + j) * DH + dd] =
                make_float4(o[r][0], o[r][1], o[r][2], o[r][3]);
        }
    }

    {
        int r = tid >> 2, h2 = tid & 3;
        float acc = 0.f;
        #pragma unroll 8
        for (int kk = 0; kk < CDIM; kk++)
            acc += xsT[kk * 68 + r] * wbs[kk * NH + h2];
        g_bias[(size_t)h2 * NN + Rb + r] = acc;
    }
}

// =====================================================================
// Kernel B: attention per (i,h) using tf32 mma.sync.
// 256 threads = 8 warps = 4 pairs. Pass: 64 q (pair=16q), 5 passes.
// Warp tile: 16q x 160kj (half of kj axis), merged softmax across pair.
// =====================================================================
// smem float offsets
#define KS_OFF   0                              // [320][36] tf32 bits
#define VS_OFF   (KS_OFF + 320*36)              // [320][36] tf32 bits
#define QS_OFF   (VS_OFF + 320*36)              // [64][36] tf32 bits
#define PS_OFF   (QS_OFF + 64*36)               // 8 warps x [16][164] tf32 bits
#define MSK_OFF  (PS_OFF + 8*16*164)            // [320] f32
#define RED_OFF  (MSK_OFF + 320)                // 8 warps x 16 rows x {m,s}
#define OPART_OFF (RED_OFF + 8*16*2)            // 4 pairs x [16][32]
#define SMEM_B   ((OPART_OFF + 4*16*32) * 4)

__global__ __launch_bounds__(256, 1) void kB(const float* __restrict__ mask)
{
    extern __shared__ float sm[];
    uint32_t* ksu = (uint32_t*)(sm + KS_OFF);
    uint32_t* vsu = (uint32_t*)(sm + VS_OFF);
    uint32_t* qsu = (uint32_t*)(sm + QS_OFF);
    uint32_t* psu = (uint32_t*)(sm + PS_OFF);
    float* msk   = sm + MSK_OFF;
    float* red   = sm + RED_OFF;
    float* opart = sm + OPART_OFF;

    int i = blockIdx.x, h = blockIdx.y;
    int tid = threadIdx.x, lane = tid & 31, w = tid >> 5;
    int p2 = w >> 1, half = w & 1;
    int khalf = half * 160;
    int g = lane >> 2, c = lane & 3;

    size_t base = ((size_t)i * NH + h) * (NRES * DH);
    const float* kg = g_k    + base;
    const float* qg = g_q    + base;
    const float* vg = g_v    + base;
    const float* gg = g_gate + base;

    // stage K, V as tf32
    for (int idx = tid; idx < NRES * DH; idx += 256) {
        int kk = idx >> 5, d = idx & 31;
        ksu[kk * 36 + d] = f2tf(kg[idx]);
        vsu[kk * 36 + d] = f2tf(vg[idx]);
    }
    for (int idx = tid; idx < NRES; idx += 256)
        msk[idx] = 1.0e9f * (mask[(size_t)i * NRES + idx] - 1.f);

    const float* bias_h = g_bias + (size_t)h * NN;
    uint32_t* pw = psu + w * 16 * 164;

    __syncthreads();

    #pragma unroll 1
    for (int p = 0; p < 5; p++) {
        int qpass = p * 64;
        int qsub  = p2 * 16;
        int qbase = qpass + qsub;

        // ---- stage q tile (64 rows) as tf32 ----
        for (int idx = tid; idx < 64 * DH; idx += 256) {
            int r = idx >> 5, d = idx & 31;
            qsu[r * 36 + d] = f2tf(qg[(qpass + r) * DH + d]);
        }
        __syncthreads();

        // ---- S = Q_tile x K_half^T : 20 n-tiles x 4 k-steps ----
        float s[20][4];
        #pragma unroll
        for (int t = 0; t < 20; t++)
            #pragma unroll
            for (int e = 0; e < 4; e++) s[t][e] = 0.f;

        #pragma unroll
        for (int ds = 0; ds < 4; ds++) {
            int dc = ds * 8;
            uint32_t a0 = qsu[(qsub + g)     * 36 + dc + c];
            uint32_t a1 = qsu[(qsub + g + 8) * 36 + dc + c];
            uint32_t a2 = qsu[(qsub + g)     * 36 + dc + c + 4];
            uint32_t a3 = qsu[(qsub + g + 8) * 36 + dc + c + 4];
            #pragma unroll
            for (int t = 0; t < 20; t++) {
                int n0 = (khalf + t * 8 + g) * 36 + dc;
                uint32_t b0 = ksu[n0 + c];
                uint32_t b1 = ksu[n0 + c + 4];
                mma_tf32(s[t], a0, a1, a2, a3, b0, b1);
            }
        }

        // ---- bias + mask ----
        int row0 = qbase + g, row1 = row0 + 8;
        #pragma unroll
        for (int t = 0; t < 20; t++) {
            int col = khalf + t * 8 + c * 2;
            float2 mk = *(const float2*)&msk[col];
            float2 bA = __ldg((const float2*)&bias_h[(size_t)row0 * NRES + col]);
            float2 bB = __ldg((const float2*)&bias_h[(size_t)row1 * NRES + col]);
            s[t][0] += bA.x + mk.x;  s[t][1] += bA.y + mk.y;
            s[t][2] += bB.x + mk.x;  s[t][3] += bB.y + mk.y;
        }

        // ---- local softmax over 160 (rows row0, row1) ----
        float mA = -1e30f, mB = -1e30f;
        #pragma unroll
        for (int t = 0; t < 20; t++) {
            mA = fmaxf(mA, fmaxf(s[t][0], s[t][1]));
            mB = fmaxf(mB, fmaxf(s[t][2], s[t][3]));
        }
        mA = fmaxf(mA, __shfl_xor_sync(0xffffffffu, mA, 1));
        mB = fmaxf(mB, __shfl_xor_sync(0xffffffffu, mB, 1));
        mA = fmaxf(mA, __shfl_xor_sync(0xffffffffu, mA, 2));
        mB = fmaxf(mB, __shfl_xor_sync(0xffffffffu, mB, 2));

        float sA = 0.f, sB = 0.f;
        #pragma unroll
        for (int t = 0; t < 20; t++) {
            s[t][0] = __expf(s[t][0] - mA); sA += s[t][0];
            s[t][1] = __expf(s[t][1] - mA); sA += s[t][1];
            s[t][2] = __expf(s[t][2] - mB); sB += s[t][2];
            s[t][3] = __expf(s[t][3] - mB); sB += s[t][3];
        }
        sA += __shfl_xor_sync(0xffffffffu, sA, 1);
        sB += __shfl_xor_sync(0xffffffffu, sB, 1);
        sA += __shfl_xor_sync(0xffffffffu, sA, 2);
        sB += __shfl_xor_sync(0xffffffffu, sB, 2);

        if (c == 0) {
            red[(w * 16 + g)     * 2]     = mA;
            red[(w * 16 + g)     * 2 + 1] = sA;
            red[(w * 16 + g + 8) * 2]     = mB;
            red[(w * 16 + g + 8) * 2 + 1] = sB;
        }
        __syncthreads();

        // ---- merge with partner half ----
        int wo = w ^ 1;
        float moA = red[(wo * 16 + g) * 2],     soA = red[(wo * 16 + g) * 2 + 1];
        float moB = red[(wo * 16 + g + 8) * 2], soB = red[(wo * 16 + g + 8) * 2 + 1];
        float MA = fmaxf(mA, moA), MB = fmaxf(mB, moB);
        float eA = __expf(mA - MA), eB = __expf(mB - MB);
        float facA = eA / (sA * eA + soA * __expf(moA - MA));
        float facB = eB / (sB * eB + soB * __expf(moB - MB));

        // ---- P (scaled, tf32) to per-warp smem ----
        #pragma unroll
        for (int t = 0; t < 20; t++) {
            int kl = t * 8 + c * 2;
            uint32_t p0 = f2tf(s[t][0] * facA);
            uint32_t p1 = f2tf(s[t][1] * facA);
            uint32_t p2_ = f2tf(s[t][2] * facB);
            uint32_t p3 = f2tf(s[t][3] * facB);
            *(uint2*)&pw[g * 164 + kl]       = make_uint2(p0, p1);
            *(uint2*)&pw[(g + 8) * 164 + kl] = make_uint2(p2_, p3);
        }
        __syncwarp();

        // ---- O = P x V_half : 4 n-tiles x 20 k-steps ----
        float o[4][4];
        #pragma unroll
        for (int t = 0; t < 4; t++)
            #pragma unroll
            for (int e = 0; e < 4; e++) o[t][e] = 0.f;

        #pragma unroll 4
        for (int ks = 0; ks < 20; ks++) {
            int kc = ks * 8;
            uint32_t a0 = pw[g * 164 + kc + c];
            uint32_t a1 = pw[(g + 8) * 164 + kc + c];
            uint32_t a2 = pw[g * 164 + kc + c + 4];
            uint32_t a3 = pw[(g + 8) * 164 + kc + c + 4];
            int vr0 = (khalf + kc + c) * 36;
            int vr1 = (khalf + kc + c + 4) * 36;
            #pragma unroll
            for (int t = 0; t < 4; t++) {
                uint32_t b0 = vsu[vr0 + t * 8 + g];
                uint32_t b1 = vsu[vr1 + t * 8 + g];
                mma_tf32(o[t], a0, a1, a2, a3, b0, b1);
            }
        }

        // ---- pair merge + gate + store ----
        if (half) {
            #pragma unroll
            for (int t = 0; t < 4; t++) {
                int col = t * 8 + c * 2;
                *(float2*)&opart[(p2 * 16 + g) * 32 + col]     = make_float2(o[t][0], o[t][1]);
                *(float2*)&opart[(p2 * 16 + g + 8) * 32 + col] = make_float2(o[t][2], o[t][3]);
            }
        }
        __syncthreads();
        if (!half) {
            #pragma unroll
            for (int t = 0; t < 4; t++) {
                int col = t * 8 + c * 2;
                float2 qa = *(const float2*)&opart[(p2 * 16 + g) * 32 + col];
                float2 qb = *(const float2*)&opart[(p2 * 16 + g + 8) * 32 + col];
                float2 gA = __ldg((const float2*)&gg[row0 * 32 + col]);
                float2 gB = __ldg((const float2*)&gg[row1 * 32 + col]);
                float2 rA = make_float2((o[t][0] + qa.x) * gA.x, (o[t][1] + qa.y) * gA.y);
                float2 rB = make_float2((o[t][2] + qb.x) * gB.x, (o[t][3] + qb.y) * gB.y);
                *(float2*)&g_og[((size_t)i * NRES + row0) * CDIM + h * DH + col] = rA;
                *(float2*)&g_og[((size_t)i * NRES + row1) * CDIM + h * DH + col] = rB;
            }
        }
        __syncthreads();
    }
}

// =====================================================================
// Kernel C: output projection (unchanged)
// =====================================================================
__global__ __launch_bounds__(256, 2) void kC(
    const float* __restrict__ wo, const float* __restrict__ bo,
    float* __restrict__ out)
{
    __shared__ float oT[CDIM*68];
    int tid = threadIdx.x;
    int Rb = blockIdx.x * 64;

    for (int idx = tid; idx < 64 * CDIM; idx += 256) {
        int r = idx >> 7, c = idx & 127;
        oT[c * 68 + r] = g_og[(size_t)(Rb + r) * CDIM + c];
    }
    __syncthreads();

    int tx = tid & 31, ty = tid >> 5;
    int col4 = tx * 4, row8 = ty * 8;
    uint32_t oT_a = s2u(oT) + row8 * 4;

    u64 acc[4][4];
    #pragma unroll
    for (int r = 0; r < 4; r++)
        #pragma unroll
        for (int c = 0; c < 4; c++) acc[r][c] = 0ull;

    #pragma unroll 4
    for (int kk = 0; kk < CDIM; kk++) {
        u64 av[4];
        lds2(av[0], av[1], oT_a + kk * 272);
        lds2(av[2], av[3], oT_a + kk * 272 + 16);
        float4 b = __ldg((const float4*)&wo[kk * CDIM + col4]);
        u64 bd[4] = { pk(b.x,b.x), pk(b.y,b.y), pk(b.z,b.z), pk(b.w,b.w) };
        #pragma unroll
        for (int r = 0; r < 4; r++)
            #pragma unroll
            for (int c = 0; c < 4; c++)
                fma2(acc[r][c], av[r], bd[c]);
    }

    float4 bb = *(const float4*)&bo[col4];
    float bvv[4] = {bb.x, bb.y, bb.z, bb.w};
    #pragma unroll
    for (int r = 0; r < 4; r++) {
        float2 t0 = up(acc[r][0]), t1 = up(acc[r][1]), t2 = up(acc[r][2]), t3 = up(acc[r][3]);
        *(float4*)&out[(size_t)(Rb + row8 + 2*r) * CDIM + col4] =
            make_float4(t0.x + bvv[0], t1.x + bvv[1], t2.x + bvv[2], t3.x + bvv[3]);
        *(float4*)&out[(size_t)(Rb + row8 + 2*r + 1) * CDIM + col4] =
            make_float4(t0.y + bvv[0], t1.y + bvv[1], t2.y + bvv[2], t3.y + bvv[3]);
    }
}

// =====================================================================
extern "C" void kernel_launch(void* const* d_in, const int* in_sizes, int n_in,
                              void* d_out, int out_size)
{
    const float* x    = (const float*)d_in[0];
    const float* mask = (const float*)d_in[1];
    const float* lng  = (const float*)d_in[2];
    const float* lnb  = (const float*)d_in[3];
    const float* wb   = (const float*)d_in[4];
    const float* wq   = (const float*)d_in[5];
    const float* wk   = (const float*)d_in[6];
    const float* wv   = (const float*)d_in[7];
    const float* wg   = (const float*)d_in[8];
    const float* bg   = (const float*)d_in[9];
    const float* wo   = (const float*)d_in[10];
    const float* bo   = (const float*)d_in[11];
    float* out = (float*)d_out;

    cudaFuncSetAttribute(kB, cudaFuncAttributeMaxDynamicSharedMemorySize, SMEM_B);

    kA<<<NN / 64, 256>>>(x, lng, lnb, wb, wq, wk, wv, wg, bg);
    kB<<<dim3(NRES, NH), 256, SMEM_B>>>(mask);
    kC<<<NN / 64, 256>>>(wo, bo, out);
}

// round 6
// speedup vs baseline: 1.6204x; 1.0046x over previous
#include <cuda_runtime.h>
#include <cstdint>

#define NRES 320
#define CDIM 128
#define NH 4
#define DH 32
#define NN (NRES*NRES)
#define AP 132   // padded row stride for MMA smem tiles

// ---------- tf32 mma helpers ----------
__device__ __forceinline__ uint32_t f2tf(float f) {
    uint32_t u; asm("cvt.rna.tf32.f32 %0, %1;" : "=r"(u) : "f"(f)); return u;
}
__device__ __forceinline__ void mma_tf32(float* d,
    uint32_t a0, uint32_t a1, uint32_t a2, uint32_t a3,
    uint32_t b0, uint32_t b1)
{
    asm volatile(
        "mma.sync.aligned.m16n8k8.row.col.f32.tf32.tf32.f32 "
        "{%0,%1,%2,%3}, {%4,%5,%6,%7}, {%8,%9}, {%0,%1,%2,%3};"
        : "+f"(d[0]), "+f"(d[1]), "+f"(d[2]), "+f"(d[3])
        : "r"(a0), "r"(a1), "r"(a2), "r"(a3), "r"(b0), "r"(b1));
}

// -------- device scratch --------
__device__ float g_q   [(size_t)NRES*NH*NRES*DH];   // [i][h][j][d]
__device__ float g_k   [(size_t)NRES*NH*NRES*DH];
__device__ float g_v   [(size_t)NRES*NH*NRES*DH];
__device__ float g_gate[(size_t)NRES*NH*NRES*DH];
__device__ float g_og  [(size_t)NN*CDIM];
__device__ float g_bias[(size_t)NH*NN];             // [h][q][j]

// =====================================================================
// Kernel A (tensor): LN + q/k/v/gate projections + tri bias.
// 128 rows/block, 256 threads, 2-term split-A tf32 MMA, W chunked in smem.
// =====================================================================
#define KA_AHI 0
#define KA_ALO (KA_AHI + 128*AP)
#define KA_WT  (KA_ALO + 128*AP)
#define KA_SG  (KA_WT  + 128*AP)
#define KA_SB  (KA_SG + 128)
#define KA_WB  (KA_SB + 128)
#define SMEM_A ((KA_WB + 512) * 4)

__global__ __launch_bounds__(256, 1) void kA(
    const float* __restrict__ x,   const float* __restrict__ lng,
    const float* __restrict__ lnb, const float* __restrict__ wb,
    const float* __restrict__ wq,  const float* __restrict__ wk,
    const float* __restrict__ wv,  const float* __restrict__ wg,
    const float* __restrict__ bg)
{
    extern __shared__ float sm[];
    float* ahi_f = sm + KA_AHI;
    float* alo_f = sm + KA_ALO;
    float* wt_f  = sm + KA_WT;
    float* sg    = sm + KA_SG;
    float* sb    = sm + KA_SB;
    float* wbs   = sm + KA_WB;
    uint32_t* ahi = (uint32_t*)ahi_f;
    uint32_t* alo = (uint32_t*)alo_f;
    uint32_t* wt  = (uint32_t*)wt_f;

    int tid = threadIdx.x, lane = tid & 31, w = tid >> 5;
    int g2 = lane >> 2, cq = lane & 3;
    int Rb = blockIdx.x * 128;

    if (tid < 128) { sg[tid] = lng[tid]; sb[tid] = lnb[tid]; }
    for (int idx = tid; idx < 512; idx += 256) wbs[idx] = wb[idx];

    // ---- layernorm: 2 threads per row (64 elems each) ----
    int row = tid >> 1, sub = tid & 1;
    float xv[64];
    const float* xr = x + (size_t)(Rb + row) * CDIM + sub * 64;
    #pragma unroll
    for (int m4 = 0; m4 < 16; m4++) {
        float4 t = *(const float4*)(xr + m4 * 4);
        xv[m4*4+0] = t.x; xv[m4*4+1] = t.y; xv[m4*4+2] = t.z; xv[m4*4+3] = t.w;
    }
    float sum = 0.f, sq = 0.f;
    #pragma unroll
    for (int m = 0; m < 64; m++) { sum += xv[m]; sq += xv[m]*xv[m]; }
    sum += __shfl_xor_sync(0xffffffffu, sum, 1, 2);
    sq  += __shfl_xor_sync(0xffffffffu, sq,  1, 2);
    float mu = sum * (1.f / CDIM);
    float rs = rsqrtf(sq * (1.f / CDIM) - mu * mu + 1e-5f);

    __syncthreads();   // sg/sb ready
    #pragma unroll
    for (int m = 0; m < 64; m++) {
        int c = sub * 64 + m;
        float val = (xv[m] - mu) * rs * sg[c] + sb[c];
        uint32_t hb = f2tf(val);
        float hf = __uint_as_float(hb);
        ahi[row * AP + c] = hb;
        alo[row * AP + c] = f2tf(val - hf);
    }
    __syncthreads();   // A ready

    // ---- triangle bias: 512 items, 2 per thread ----
    #pragma unroll
    for (int rep = 0; rep < 2; rep++) {
        int it = tid + rep * 256;
        int r = it >> 2, h2 = it & 3;
        float acc = 0.f;
        #pragma unroll 8
        for (int kk = 0; kk < CDIM; kk++)
            acc += (ahi_f[r * AP + kk] + alo_f[r * AP + kk]) * wbs[kk * NH + h2];
        g_bias[(size_t)h2 * NN + Rb + r] = acc;
    }

    // ---- 4 projection chunks ----
    int r0 = (w << 4) + g2;
    int R0 = Rb + r0, R1 = R0 + 8;
    int i0 = R0 / NRES, j0 = R0 - i0 * NRES;
    int i1 = R1 / NRES, j1 = R1 - i1 * NRES;

    #pragma unroll 1
    for (int s = 0; s < 4; s++) {
        const float* W = (s == 0) ? wq : (s == 1) ? wk : (s == 2) ? wv : wg;
        // stage Wt transposed tf32: wt[n][k]
        for (int idx = tid; idx < 128 * 128; idx += 256) {
            int k = idx >> 7, n = idx & 127;
            wt[n * AP + k] = f2tf(W[k * 128 + n]);
        }
        __syncthreads();

        float acc[16][4];
        #pragma unroll
        for (int t = 0; t < 16; t++)
            #pragma unroll
            for (int e = 0; e < 4; e++) acc[t][e] = 0.f;

        #pragma unroll 4
        for (int ks = 0; ks < 16; ks++) {
            int kc = ks * 8;
            uint32_t h0 = ahi[r0 * AP + kc + cq];
            uint32_t h1 = ahi[(r0 + 8) * AP + kc + cq];
            uint32_t h2_ = ahi[r0 * AP + kc + cq + 4];
            uint32_t h3 = ahi[(r0 + 8) * AP + kc + cq + 4];
            uint32_t l0 = alo[r0 * AP + kc + cq];
            uint32_t l1 = alo[(r0 + 8) * AP + kc + cq];
            uint32_t l2 = alo[r0 * AP + kc + cq + 4];
            uint32_t l3 = alo[(r0 + 8) * AP + kc + cq + 4];
            #pragma unroll
            for (int t = 0; t < 16; t++) {
                int n0 = (t * 8 + g2) * AP + kc;
                uint32_t b0 = wt[n0 + cq];
                uint32_t b1 = wt[n0 + cq + 4];
                mma_tf32(acc[t], h0, h1, h2_, h3, b0, b1);
                mma_tf32(acc[t], l0, l1, l2, l3, b0, b1);
            }
        }

        // epilogue
        if (s == 0) {
            #pragma unroll
            for (int t = 0; t < 16; t++)
                #pragma unroll
                for (int e = 0; e < 4; e++) acc[t][e] *= 0.17677669529663687f;
        }
        if (s == 3) {
            #pragma unroll
            for (int t = 0; t < 16; t++) {
                int col = t * 8 + cq * 2;
                float2 bgv = __ldg((const float2*)&bg[col]);
                acc[t][0] = 1.f / (1.f + __expf(-(acc[t][0] + bgv.x)));
                acc[t][1] = 1.f / (1.f + __expf(-(acc[t][1] + bgv.y)));
                acc[t][2] = 1.f / (1.f + __expf(-(acc[t][2] + bgv.x)));
                acc[t][3] = 1.f / (1.f + __expf(-(acc[t][3] + bgv.y)));
            }
        }
        float* dst = (s == 0) ? g_q : (s == 1) ? g_k : (s == 2) ? g_v : g_gate;
        #pragma unroll
        for (int t = 0; t < 16; t++) {
            int col = t * 8 + cq * 2;
            int h = col >> 5, d = col & 31;
            *(float2*)&dst[(((size_t)i0 * NH + h) * NRES + j0) * DH + d] =
                make_float2(acc[t][0], acc[t][1]);
            *(float2*)&dst[(((size_t)i1 * NH + h) * NRES + j1) * DH + d] =
                make_float2(acc[t][2], acc[t][3]);
        }
        __syncthreads();   // protect wt overwrite
    }
}

// =====================================================================
// Kernel B: attention per (i,h) using tf32 mma.sync (unchanged from R5)
// =====================================================================
#define KS_OFF   0
#define VS_OFF   (KS_OFF + 320*36)
#define QS_OFF   (VS_OFF + 320*36)
#define PS_OFF   (QS_OFF + 64*36)
#define MSK_OFF  (PS_OFF + 8*16*164)
#define RED_OFF  (MSK_OFF + 320)
#define OPART_OFF (RED_OFF + 8*16*2)
#define SMEM_B   ((OPART_OFF + 4*16*32) * 4)

__global__ __launch_bounds__(256, 1) void kB(const float* __restrict__ mask)
{
    extern __shared__ float sm[];
    uint32_t* ksu = (uint32_t*)(sm + KS_OFF);
    uint32_t* vsu = (uint32_t*)(sm + VS_OFF);
    uint32_t* qsu = (uint32_t*)(sm + QS_OFF);
    uint32_t* psu = (uint32_t*)(sm + PS_OFF);
    float* msk   = sm + MSK_OFF;
    float* red   = sm + RED_OFF;
    float* opart = sm + OPART_OFF;

    int i = blockIdx.x, h = blockIdx.y;
    int tid = threadIdx.x, lane = tid & 31, w = tid >> 5;
    int p2 = w >> 1, half = w & 1;
    int khalf = half * 160;
    int g = lane >> 2, c = lane & 3;

    size_t base = ((size_t)i * NH + h) * (NRES * DH);
    const float* kg = g_k    + base;
    const float* qg = g_q    + base;
    const float* vg = g_v    + base;
    const float* gg = g_gate + base;

    for (int idx = tid; idx < NRES * DH; idx += 256) {
        int kk = idx >> 5, d = idx & 31;
        ksu[kk * 36 + d] = f2tf(kg[idx]);
        vsu[kk * 36 + d] = f2tf(vg[idx]);
    }
    for (int idx = tid; idx < NRES; idx += 256)
        msk[idx] = 1.0e9f * (mask[(size_t)i * NRES + idx] - 1.f);

    const float* bias_h = g_bias + (size_t)h * NN;
    uint32_t* pw = psu + w * 16 * 164;

    __syncthreads();

    #pragma unroll 1
    for (int p = 0; p < 5; p++) {
        int qpass = p * 64;
        int qsub  = p2 * 16;
        int qbase = qpass + qsub;

        for (int idx = tid; idx < 64 * DH; idx += 256) {
            int r = idx >> 5, d = idx & 31;
            qsu[r * 36 + d] = f2tf(qg[(qpass + r) * DH + d]);
        }
        __syncthreads();

        float s[20][4];
        #pragma unroll
        for (int t = 0; t < 20; t++)
            #pragma unroll
            for (int e = 0; e < 4; e++) s[t][e] = 0.f;

        #pragma unroll
        for (int ds = 0; ds < 4; ds++) {
            int dc = ds * 8;
            uint32_t a0 = qsu[(qsub + g)     * 36 + dc + c];
            uint32_t a1 = qsu[(qsub + g + 8) * 36 + dc + c];
            uint32_t a2 = qsu[(qsub + g)     * 36 + dc + c + 4];
            uint32_t a3 = qsu[(qsub + g + 8) * 36 + dc + c + 4];
            #pragma unroll
            for (int t = 0; t < 20; t++) {
                int n0 = (khalf + t * 8 + g) * 36 + dc;
                uint32_t b0 = ksu[n0 + c];
                uint32_t b1 = ksu[n0 + c + 4];
                mma_tf32(s[t], a0, a1, a2, a3, b0, b1);
            }
        }

        int row0 = qbase + g, row1 = row0 + 8;
        #pragma unroll
        for (int t = 0; t < 20; t++) {
            int col = khalf + t * 8 + c * 2;
            float2 mk = *(const float2*)&msk[col];
            float2 bA = __ldg((const float2*)&bias_h[(size_t)row0 * NRES + col]);
            float2 bB = __ldg((const float2*)&bias_h[(size_t)row1 * NRES + col]);
            s[t][0] += bA.x + mk.x;  s[t][1] += bA.y + mk.y;
            s[t][2] += bB.x + mk.x;  s[t][3] += bB.y + mk.y;
        }

        float mA = -1e30f, mB = -1e30f;
        #pragma unroll
        for (int t = 0; t < 20; t++) {
            mA = fmaxf(mA, fmaxf(s[t][0], s[t][1]));
            mB = fmaxf(mB, fmaxf(s[t][2], s[t][3]));
        }
        mA = fmaxf(mA, __shfl_xor_sync(0xffffffffu, mA, 1));
        mB = fmaxf(mB, __shfl_xor_sync(0xffffffffu, mB, 1));
        mA = fmaxf(mA, __shfl_xor_sync(0xffffffffu, mA, 2));
        mB = fmaxf(mB, __shfl_xor_sync(0xffffffffu, mB, 2));

        float sA = 0.f, sB = 0.f;
        #pragma unroll
        for (int t = 0; t < 20; t++) {
            s[t][0] = __expf(s[t][0] - mA); sA += s[t][0];
            s[t][1] = __expf(s[t][1] - mA); sA += s[t][1];
            s[t][2] = __expf(s[t][2] - mB); sB += s[t][2];
            s[t][3] = __expf(s[t][3] - mB); sB += s[t][3];
        }
        sA += __shfl_xor_sync(0xffffffffu, sA, 1);
        sB += __shfl_xor_sync(0xffffffffu, sB, 1);
        sA += __shfl_xor_sync(0xffffffffu, sA, 2);
        sB += __shfl_xor_sync(0xffffffffu, sB, 2);

        if (c == 0) {
            red[(w * 16 + g)     * 2]     = mA;
            red[(w * 16 + g)     * 2 + 1] = sA;
            red[(w * 16 + g + 8) * 2]     = mB;
            red[(w * 16 + g + 8) * 2 + 1] = sB;
        }
        __syncthreads();

        int wo = w ^ 1;
        float moA = red[(wo * 16 + g) * 2],     soA = red[(wo * 16 + g) * 2 + 1];
        float moB = red[(wo * 16 + g + 8) * 2], soB = red[(wo * 16 + g + 8) * 2 + 1];
        float MA = fmaxf(mA, moA), MB = fmaxf(mB, moB);
        float eA = __expf(mA - MA), eB = __expf(mB - MB);
        float facA = eA / (sA * eA + soA * __expf(moA - MA));
        float facB = eB / (sB * eB + soB * __expf(moB - MB));

        #pragma unroll
        for (int t = 0; t < 20; t++) {
            int kl = t * 8 + c * 2;
            uint32_t p0 = f2tf(s[t][0] * facA);
            uint32_t p1 = f2tf(s[t][1] * facA);
            uint32_t p2_ = f2tf(s[t][2] * facB);
            uint32_t p3 = f2tf(s[t][3] * facB);
            *(uint2*)&pw[g * 164 + kl]       = make_uint2(p0, p1);
            *(uint2*)&pw[(g + 8) * 164 + kl] = make_uint2(p2_, p3);
        }
        __syncwarp();

        float o[4][4];
        #pragma unroll
        for (int t = 0; t < 4; t++)
            #pragma unroll
            for (int e = 0; e < 4; e++) o[t][e] = 0.f;

        #pragma unroll 4
        for (int ks = 0; ks < 20; ks++) {
            int kc = ks * 8;
            uint32_t a0 = pw[g * 164 + kc + c];
            uint32_t a1 = pw[(g + 8) * 164 + kc + c];
            uint32_t a2 = pw[g * 164 + kc + c + 4];
            uint32_t a3 = pw[(g + 8) * 164 + kc + c + 4];
            int vr0 = (khalf + kc + c) * 36;
            int vr1 = (khalf + kc + c + 4) * 36;
            #pragma unroll
            for (int t = 0; t < 4; t++) {
                uint32_t b0 = vsu[vr0 + t * 8 + g];
                uint32_t b1 = vsu[vr1 + t * 8 + g];
                mma_tf32(o[t], a0, a1, a2, a3, b0, b1);
            }
        }

        if (half) {
            #pragma unroll
            for (int t = 0; t < 4; t++) {
                int col = t * 8 + c * 2;
                *(float2*)&opart[(p2 * 16 + g) * 32 + col]     = make_float2(o[t][0], o[t][1]);
                *(float2*)&opart[(p2 * 16 + g + 8) * 32 + col] = make_float2(o[t][2], o[t][3]);
            }
        }
        __syncthreads();
        if (!half) {
            #pragma unroll
            for (int t = 0; t < 4; t++) {
                int col = t * 8 + c * 2;
                float2 qa = *(const float2*)&opart[(p2 * 16 + g) * 32 + col];
                float2 qb = *(const float2*)&opart[(p2 * 16 + g + 8) * 32 + col];
                float2 gA = __ldg((const float2*)&gg[row0 * 32 + col]);
                float2 gB = __ldg((const float2*)&gg[row1 * 32 + col]);
                float2 rA = make_float2((o[t][0] + qa.x) * gA.x, (o[t][1] + qa.y) * gA.y);
                float2 rB = make_float2((o[t][2] + qb.x) * gB.x, (o[t][3] + qb.y) * gB.y);
                *(float2*)&g_og[((size_t)i * NRES + row0) * CDIM + h * DH + col] = rA;
                *(float2*)&g_og[((size_t)i * NRES + row1) * CDIM + h * DH + col] = rB;
            }
        }
        __syncthreads();
    }
}

// =====================================================================
// Kernel C (tensor): out = og @ wo + bo. 128 rows/block, tf32 single.
// =====================================================================
#define KC_A  0
#define KC_WT (KC_A + 128*AP)
#define SMEM_C ((KC_WT + 128*AP) * 4)

__global__ __launch_bounds__(256, 1) void kC(
    const float* __restrict__ wo, const float* __restrict__ bo,
    float* __restrict__ out)
{
    extern __shared__ float sm[];
    uint32_t* ao = (uint32_t*)(sm + KC_A);
    uint32_t* wt = (uint32_t*)(sm + KC_WT);

    int tid = threadIdx.x, lane = tid & 31, w = tid >> 5;
    int g2 = lane >> 2, cq = lane & 3;
    int Rb = blockIdx.x * 128;

    for (int idx = tid; idx < 128 * 128; idx += 256) {
        int r = idx >> 7, c = idx & 127;
        ao[r * AP + c] = f2tf(g_og[(size_t)(Rb + r) * CDIM + c]);
        int k = idx >> 7, n = idx & 127;
        wt[n * AP + k] = f2tf(wo[k * 128 + n]);
    }
    __syncthreads();

    int r0 = (w << 4) + g2;

    float acc[16][4];
    #pragma unroll
    for (int t = 0; t < 16; t++)
        #pragma unroll
        for (int e = 0; e < 4; e++) acc[t][e] = 0.f;

    #pragma unroll 4
    for (int ks = 0; ks < 16; ks++) {
        int kc = ks * 8;
        uint32_t a0 = ao[r0 * AP + kc + cq];
        uint32_t a1 = ao[(r0 + 8) * AP + kc + cq];
        uint32_t a2 = ao[r0 * AP + kc + cq + 4];
        uint32_t a3 = ao[(r0 + 8) * AP + kc + cq + 4];
        #pragma unroll
        for (int t = 0; t < 16; t++) {
            int n0 = (t * 8 + g2) * AP + kc;
            uint32_t b0 = wt[n0 + cq];
            uint32_t b1 = wt[n0 + cq + 4];
            mma_tf32(acc[t], a0, a1, a2, a3, b0, b1);
        }
    }

    #pragma unroll
    for (int t = 0; t < 16; t++) {
        int col = t * 8 + cq * 2;
        float2 bb = __ldg((const float2*)&bo[col]);
        *(float2*)&out[(size_t)(Rb + r0) * CDIM + col] =
            make_float2(acc[t][0] + bb.x, acc[t][1] + bb.y);
        *(float2*)&out[(size_t)(Rb + r0 + 8) * CDIM + col] =
            make_float2(acc[t][2] + bb.x, acc[t][3] + bb.y);
    }
}

// =====================================================================
extern "C" void kernel_launch(void* const* d_in, const int* in_sizes, int n_in,
                              void* d_out, int out_size)
{
    const float* x    = (const float*)d_in[0];
    const float* mask = (const float*)d_in[1];
    const float* lng  = (const float*)d_in[2];
    const float* lnb  = (const float*)d_in[3];
    const float* wb   = (const float*)d_in[4];
    const float* wq   = (const float*)d_in[5];
    const float* wk   = (const float*)d_in[6];
    const float* wv   = (const float*)d_in[7];
    const float* wg   = (const float*)d_in[8];
    const float* bg   = (const float*)d_in[9];
    const float* wo   = (const float*)d_in[10];
    const float* bo   = (const float*)d_in[11];
    float* out = (float*)d_out;

    cudaFuncSetAttribute(kA, cudaFuncAttributeMaxDynamicSharedMemorySize, SMEM_A);
    cudaFuncSetAttribute(kB, cudaFuncAttributeMaxDynamicSharedMemorySize, SMEM_B);
    cudaFuncSetAttribute(kC, cudaFuncAttributeMaxDynamicSharedMemorySize, SMEM_C);

    kA<<<NN / 128, 256, SMEM_A>>>(x, lng, lnb, wb, wq, wk, wv, wg, bg);
    kB<<<dim3(NRES, NH), 256, SMEM_B>>>(mask);
    kC<<<NN / 128, 256, SMEM_C>>>(wo, bo, out);
}

// round 8
// speedup vs baseline: 1.7755x; 1.0957x over previous
#include <cuda_runtime.h>
#include <cstdint>

#define NRES 320
#define CDIM 128
#define NH 4
#define DH 32
#define NN (NRES*NRES)
#define AP 132   // padded row stride for MMA smem tiles

// ---------- tf32 mma helpers ----------
__device__ __forceinline__ uint32_t f2tf(float f) {
    uint32_t u; asm("cvt.rna.tf32.f32 %0, %1;" : "=r"(u) : "f"(f)); return u;
}
__device__ __forceinline__ void mma_tf32(float* d,
    uint32_t a0, uint32_t a1, uint32_t a2, uint32_t a3,
    uint32_t b0, uint32_t b1)
{
    asm volatile(
        "mma.sync.aligned.m16n8k8.row.col.f32.tf32.tf32.f32 "
        "{%0,%1,%2,%3}, {%4,%5,%6,%7}, {%8,%9}, {%0,%1,%2,%3};"
        : "+f"(d[0]), "+f"(d[1]), "+f"(d[2]), "+f"(d[3])
        : "r"(a0), "r"(a1), "r"(a2), "r"(a3), "r"(b0), "r"(b1));
}

// -------- device scratch --------
__device__ float g_q   [(size_t)NRES*NH*NRES*DH];   // [i][h][j][d]
__device__ float g_k   [(size_t)NRES*NH*NRES*DH];
__device__ float g_v   [(size_t)NRES*NH*NRES*DH];
__device__ float g_gate[(size_t)NRES*NH*NRES*DH];
__device__ float g_og  [(size_t)NN*CDIM];
__device__ float g_bias[(size_t)NH*NN];             // [h][q][j]

// =====================================================================
// Kernel A (tensor, 512 thr): LN + q/k/v/gate projections + tri bias.
// 128 rows/block, 16 warps: warp = (row-group 0..7, N-half 0..1).
// 2-term split-A tf32 MMA, W chunked into smem per projection.
// =====================================================================
#define KA_AHI 0
#define KA_ALO (KA_AHI + 128*AP)
#define KA_WT  (KA_ALO + 128*AP)
#define KA_SG  (KA_WT  + 128*AP)
#define KA_SB  (KA_SG + 128)
#define KA_WB  (KA_SB + 128)
#define SMEM_A ((KA_WB + 512) * 4)

__global__ __launch_bounds__(512, 1) void kA(
    const float* __restrict__ x,   const float* __restrict__ lng,
    const float* __restrict__ lnb, const float* __restrict__ wb,
    const float* __restrict__ wq,  const float* __restrict__ wk,
    const float* __restrict__ wv,  const float* __restrict__ wg,
    const float* __restrict__ bg)
{
    extern __shared__ float sm[];
    float* ahi_f = sm + KA_AHI;
    float* alo_f = sm + KA_ALO;
    float* sg    = sm + KA_SG;
    float* sb    = sm + KA_SB;
    float* wbs   = sm + KA_WB;
    uint32_t* ahi = (uint32_t*)ahi_f;
    uint32_t* alo = (uint32_t*)alo_f;
    uint32_t* wt  = (uint32_t*)(sm + KA_WT);

    int tid = threadIdx.x, lane = tid & 31, w = tid >> 5;
    int g2 = lane >> 2, cq = lane & 3;
    int rw = w & 7, nh = w >> 3;
    int Rb = blockIdx.x * 128;

    if (tid < 128) { sg[tid] = lng[tid]; sb[tid] = lnb[tid]; }
    // stage all 512 wb entries (fixed from R7: previous guard missed 384..511)
    wbs[tid] = wb[tid];

    // ---- layernorm: 4 threads per row (32 elems each) ----
    int row = tid >> 2, sub = tid & 3;
    float xv[32];
    const float* xr = x + (size_t)(Rb + row) * CDIM + sub * 32;
    #pragma unroll
    for (int m4 = 0; m4 < 8; m4++) {
        float4 t = *(const float4*)(xr + m4 * 4);
        xv[m4*4+0] = t.x; xv[m4*4+1] = t.y; xv[m4*4+2] = t.z; xv[m4*4+3] = t.w;
    }
    float sum = 0.f, sq = 0.f;
    #pragma unroll
    for (int m = 0; m < 32; m++) { sum += xv[m]; sq += xv[m]*xv[m]; }
    sum += __shfl_xor_sync(0xffffffffu, sum, 1, 4);
    sq  += __shfl_xor_sync(0xffffffffu, sq,  1, 4);
    sum += __shfl_xor_sync(0xffffffffu, sum, 2, 4);
    sq  += __shfl_xor_sync(0xffffffffu, sq,  2, 4);
    float mu = sum * (1.f / CDIM);
    float rs = rsqrtf(sq * (1.f / CDIM) - mu * mu + 1e-5f);

    __syncthreads();   // sg/sb ready
    #pragma unroll
    for (int m = 0; m < 32; m++) {
        int c = sub * 32 + m;
        float val = (xv[m] - mu) * rs * sg[c] + sb[c];
        uint32_t hb = f2tf(val);
        ahi[row * AP + c] = hb;
        alo[row * AP + c] = f2tf(val - __uint_as_float(hb));
    }
    __syncthreads();   // A ready

    // ---- triangle bias: 512 items, 1 per thread ----
    {
        int r = tid >> 2, h2 = tid & 3;
        float acc = 0.f;
        #pragma unroll 8
        for (int kk = 0; kk < CDIM; kk++)
            acc += (ahi_f[r * AP + kk] + alo_f[r * AP + kk]) * wbs[kk * NH + h2];
        g_bias[(size_t)h2 * NN + Rb + r] = acc;
    }

    // ---- 4 projection chunks ----
    int r0 = (rw << 4) + g2;
    int R0 = Rb + r0, R1 = R0 + 8;
    int i0 = R0 / NRES, j0 = R0 - i0 * NRES;
    int i1 = R1 / NRES, j1 = R1 - i1 * NRES;
    int colbase = nh * 64;

    #pragma unroll 1
    for (int s = 0; s < 4; s++) {
        const float* W = (s == 0) ? wq : (s == 1) ? wk : (s == 2) ? wv : wg;
        // stage Wt transposed tf32: wt[n][k]
        for (int idx = tid; idx < 128 * 128; idx += 512) {
            int k = idx >> 7, n = idx & 127;
            wt[n * AP + k] = f2tf(W[k * 128 + n]);
        }
        __syncthreads();

        float acc[8][4];
        #pragma unroll
        for (int t = 0; t < 8; t++)
            #pragma unroll
            for (int e = 0; e < 4; e++) acc[t][e] = 0.f;

        #pragma unroll 4
        for (int ks = 0; ks < 16; ks++) {
            int kc = ks * 8;
            uint32_t h0 = ahi[r0 * AP + kc + cq];
            uint32_t h1 = ahi[(r0 + 8) * AP + kc + cq];
            uint32_t h2_ = ahi[r0 * AP + kc + cq + 4];
            uint32_t h3 = ahi[(r0 + 8) * AP + kc + cq + 4];
            uint32_t l0 = alo[r0 * AP + kc + cq];
            uint32_t l1 = alo[(r0 + 8) * AP + kc + cq];
            uint32_t l2 = alo[r0 * AP + kc + cq + 4];
            uint32_t l3 = alo[(r0 + 8) * AP + kc + cq + 4];
            #pragma unroll
            for (int t = 0; t < 8; t++) {
                int n0 = (colbase + t * 8 + g2) * AP + kc;
                uint32_t b0 = wt[n0 + cq];
                uint32_t b1 = wt[n0 + cq + 4];
                mma_tf32(acc[t], h0, h1, h2_, h3, b0, b1);
                mma_tf32(acc[t], l0, l1, l2, l3, b0, b1);
            }
        }

        // epilogue
        if (s == 0) {
            #pragma unroll
            for (int t = 0; t < 8; t++)
                #pragma unroll
                for (int e = 0; e < 4; e++) acc[t][e] *= 0.17677669529663687f;
        }
        if (s == 3) {
            #pragma unroll
            for (int t = 0; t < 8; t++) {
                int col = colbase + t * 8 + cq * 2;
                float2 bgv = __ldg((const float2*)&bg[col]);
                acc[t][0] = 1.f / (1.f + __expf(-(acc[t][0] + bgv.x)));
                acc[t][1] = 1.f / (1.f + __expf(-(acc[t][1] + bgv.y)));
                acc[t][2] = 1.f / (1.f + __expf(-(acc[t][2] + bgv.x)));
                acc[t][3] = 1.f / (1.f + __expf(-(acc[t][3] + bgv.y)));
            }
        }
        float* dst = (s == 0) ? g_q : (s == 1) ? g_k : (s == 2) ? g_v : g_gate;
        #pragma unroll
        for (int t = 0; t < 8; t++) {
            int col = colbase + t * 8 + cq * 2;
            int h = col >> 5, d = col & 31;
            *(float2*)&dst[(((size_t)i0 * NH + h) * NRES + j0) * DH + d] =
                make_float2(acc[t][0], acc[t][1]);
            *(float2*)&dst[(((size_t)i1 * NH + h) * NRES + j1) * DH + d] =
                make_float2(acc[t][2], acc[t][3]);
        }
        __syncthreads();   // protect wt overwrite
    }
}

// =====================================================================
// Kernel B: attention per (i,h) using tf32 mma.sync (unchanged from R5)
// =====================================================================
#define KS_OFF   0
#define VS_OFF   (KS_OFF + 320*36)
#define QS_OFF   (VS_OFF + 320*36)
#define PS_OFF   (QS_OFF + 64*36)
#define MSK_OFF  (PS_OFF + 8*16*164)
#define RED_OFF  (MSK_OFF + 320)
#define OPART_OFF (RED_OFF + 8*16*2)
#define SMEM_B   ((OPART_OFF + 4*16*32) * 4)

__global__ __launch_bounds__(256, 1) void kB(const float* __restrict__ mask)
{
    extern __shared__ float sm[];
    uint32_t* ksu = (uint32_t*)(sm + KS_OFF);
    uint32_t* vsu = (uint32_t*)(sm + VS_OFF);
    uint32_t* qsu = (uint32_t*)(sm + QS_OFF);
    uint32_t* psu = (uint32_t*)(sm + PS_OFF);
    float* msk   = sm + MSK_OFF;
    float* red   = sm + RED_OFF;
    float* opart = sm + OPART_OFF;

    int i = blockIdx.x, h = blockIdx.y;
    int tid = threadIdx.x, lane = tid & 31, w = tid >> 5;
    int p2 = w >> 1, half = w & 1;
    int khalf = half * 160;
    int g = lane >> 2, c = lane & 3;

    size_t base = ((size_t)i * NH + h) * (NRES * DH);
    const float* kg = g_k    + base;
    const float* qg = g_q    + base;
    const float* vg = g_v    + base;
    const float* gg = g_gate + base;

    for (int idx = tid; idx < NRES * DH; idx += 256) {
        int kk = idx >> 5, d = idx & 31;
        ksu[kk * 36 + d] = f2tf(kg[idx]);
        vsu[kk * 36 + d] = f2tf(vg[idx]);
    }
    for (int idx = tid; idx < NRES; idx += 256)
        msk[idx] = 1.0e9f * (mask[(size_t)i * NRES + idx] - 1.f);

    const float* bias_h = g_bias + (size_t)h * NN;
    uint32_t* pw = psu + w * 16 * 164;

    __syncthreads();

    #pragma unroll 1
    for (int p = 0; p < 5; p++) {
        int qpass = p * 64;
        int qsub  = p2 * 16;
        int qbase = qpass + qsub;

        for (int idx = tid; idx < 64 * DH; idx += 256) {
            int r = idx >> 5, d = idx & 31;
            qsu[r * 36 + d] = f2tf(qg[(qpass + r) * DH + d]);
        }
        __syncthreads();

        float s[20][4];
        #pragma unroll
        for (int t = 0; t < 20; t++)
            #pragma unroll
            for (int e = 0; e < 4; e++) s[t][e] = 0.f;

        #pragma unroll
        for (int ds = 0; ds < 4; ds++) {
            int dc = ds * 8;
            uint32_t a0 = qsu[(qsub + g)     * 36 + dc + c];
            uint32_t a1 = qsu[(qsub + g + 8) * 36 + dc + c];
            uint32_t a2 = qsu[(qsub + g)     * 36 + dc + c + 4];
            uint32_t a3 = qsu[(qsub + g + 8) * 36 + dc + c + 4];
            #pragma unroll
            for (int t = 0; t < 20; t++) {
                int n0 = (khalf + t * 8 + g) * 36 + dc;
                uint32_t b0 = ksu[n0 + c];
                uint32_t b1 = ksu[n0 + c + 4];
                mma_tf32(s[t], a0, a1, a2, a3, b0, b1);
            }
        }

        int row0 = qbase + g, row1 = row0 + 8;
        #pragma unroll
        for (int t = 0; t < 20; t++) {
            int col = khalf + t * 8 + c * 2;
            float2 mk = *(const float2*)&msk[col];
            float2 bA = __ldg((const float2*)&bias_h[(size_t)row0 * NRES + col]);
            float2 bB = __ldg((const float2*)&bias_h[(size_t)row1 * NRES + col]);
            s[t][0] += bA.x + mk.x;  s[t][1] += bA.y + mk.y;
            s[t][2] += bB.x + mk.x;  s[t][3] += bB.y + mk.y;
        }

        float mA = -1e30f, mB = -1e30f;
        #pragma unroll
        for (int t = 0; t < 20; t++) {
            mA = fmaxf(mA, fmaxf(s[t][0], s[t][1]));
            mB = fmaxf(mB, fmaxf(s[t][2], s[t][3]));
        }
        mA = fmaxf(mA, __shfl_xor_sync(0xffffffffu, mA, 1));
        mB = fmaxf(mB, __shfl_xor_sync(0xffffffffu, mB, 1));
        mA = fmaxf(mA, __shfl_xor_sync(0xffffffffu, mA, 2));
        mB = fmaxf(mB, __shfl_xor_sync(0xffffffffu, mB, 2));

        float sA = 0.f, sB = 0.f;
        #pragma unroll
        for (int t = 0; t < 20; t++) {
            s[t][0] = __expf(s[t][0] - mA); sA += s[t][0];
            s[t][1] = __expf(s[t][1] - mA); sA += s[t][1];
            s[t][2] = __expf(s[t][2] - mB); sB += s[t][2];
            s[t][3] = __expf(s[t][3] - mB); sB += s[t][3];
        }
        sA += __shfl_xor_sync(0xffffffffu, sA, 1);
        sB += __shfl_xor_sync(0xffffffffu, sB, 1);
        sA += __shfl_xor_sync(0xffffffffu, sA, 2);
        sB += __shfl_xor_sync(0xffffffffu, sB, 2);

        if (c == 0) {
            red[(w * 16 + g)     * 2]     = mA;
            red[(w * 16 + g)     * 2 + 1] = sA;
            red[(w * 16 + g + 8) * 2]     = mB;
            red[(w * 16 + g + 8) * 2 + 1] = sB;
        }
        __syncthreads();

        int wo = w ^ 1;
        float moA = red[(wo * 16 + g) * 2],     soA = red[(wo * 16 + g) * 2 + 1];
        float moB = red[(wo * 16 + g + 8) * 2], soB = red[(wo * 16 + g + 8) * 2 + 1];
        float MA = fmaxf(mA, moA), MB = fmaxf(mB, moB);
        float eA = __expf(mA - MA), eB = __expf(mB - MB);
        float facA = eA / (sA * eA + soA * __expf(moA - MA));
        float facB = eB / (sB * eB + soB * __expf(moB - MB));

        #pragma unroll
        for (int t = 0; t < 20; t++) {
            int kl = t * 8 + c * 2;
            uint32_t p0 = f2tf(s[t][0] * facA);
            uint32_t p1 = f2tf(s[t][1] * facA);
            uint32_t p2_ = f2tf(s[t][2] * facB);
            uint32_t p3 = f2tf(s[t][3] * facB);
            *(uint2*)&pw[g * 164 + kl]       = make_uint2(p0, p1);
            *(uint2*)&pw[(g + 8) * 164 + kl] = make_uint2(p2_, p3);
        }
        __syncwarp();

        float o[4][4];
        #pragma unroll
        for (int t = 0; t < 4; t++)
            #pragma unroll
            for (int e = 0; e < 4; e++) o[t][e] = 0.f;

        #pragma unroll 4
        for (int ks = 0; ks < 20; ks++) {
            int kc = ks * 8;
            uint32_t a0 = pw[g * 164 + kc + c];
            uint32_t a1 = pw[(g + 8) * 164 + kc + c];
            uint32_t a2 = pw[g * 164 + kc + c + 4];
            uint32_t a3 = pw[(g + 8) * 164 + kc + c + 4];
            int vr0 = (khalf + kc + c) * 36;
            int vr1 = (khalf + kc + c + 4) * 36;
            #pragma unroll
            for (int t = 0; t < 4; t++) {
                uint32_t b0 = vsu[vr0 + t * 8 + g];
                uint32_t b1 = vsu[vr1 + t * 8 + g];
                mma_tf32(o[t], a0, a1, a2, a3, b0, b1);
            }
        }

        if (half) {
            #pragma unroll
            for (int t = 0; t < 4; t++) {
                int col = t * 8 + c * 2;
                *(float2*)&opart[(p2 * 16 + g) * 32 + col]     = make_float2(o[t][0], o[t][1]);
                *(float2*)&opart[(p2 * 16 + g + 8) * 32 + col] = make_float2(o[t][2], o[t][3]);
            }
        }
        __syncthreads();
        if (!half) {
            #pragma unroll
            for (int t = 0; t < 4; t++) {
                int col = t * 8 + c * 2;
                float2 qa = *(const float2*)&opart[(p2 * 16 + g) * 32 + col];
                float2 qb = *(const float2*)&opart[(p2 * 16 + g + 8) * 32 + col];
                float2 gA = __ldg((const float2*)&gg[row0 * 32 + col]);
                float2 gB = __ldg((const float2*)&gg[row1 * 32 + col]);
                float2 rA = make_float2((o[t][0] + qa.x) * gA.x, (o[t][1] + qa.y) * gA.y);
                float2 rB = make_float2((o[t][2] + qb.x) * gB.x, (o[t][3] + qb.y) * gB.y);
                *(float2*)&g_og[((size_t)i * NRES + row0) * CDIM + h * DH + col] = rA;
                *(float2*)&g_og[((size_t)i * NRES + row1) * CDIM + h * DH + col] = rB;
            }
        }
        __syncthreads();
    }
}

// =====================================================================
// Kernel C (tensor, 512 thr): out = og @ wo + bo. 128 rows/block.
// =====================================================================
#define KC_A  0
#define KC_WT (KC_A + 128*AP)
#define SMEM_C ((KC_WT + 128*AP) * 4)

__global__ __launch_bounds__(512, 1) void kC(
    const float* __restrict__ wo, const float* __restrict__ bo,
    float* __restrict__ out)
{
    extern __shared__ float sm[];
    uint32_t* ao = (uint32_t*)(sm + KC_A);
    uint32_t* wt = (uint32_t*)(sm + KC_WT);

    int tid = threadIdx.x, lane = tid & 31, w = tid >> 5;
    int g2 = lane >> 2, cq = lane & 3;
    int rw = w & 7, nh = w >> 3;
    int Rb = blockIdx.x * 128;

    for (int idx = tid; idx < 128 * 128; idx += 512) {
        int r = idx >> 7, c = idx & 127;
        ao[r * AP + c] = f2tf(g_og[(size_t)(Rb + r) * CDIM + c]);
        wt[c * AP + r] = f2tf(wo[r * 128 + c]);   // r=k, c=n
    }
    __syncthreads();

    int r0 = (rw << 4) + g2;
    int colbase = nh * 64;

    float acc[8][4];
    #pragma unroll
    for (int t = 0; t < 8; t++)
        #pragma unroll
        for (int e = 0; e < 4; e++) acc[t][e] = 0.f;

    #pragma unroll 4
    for (int ks = 0; ks < 16; ks++) {
        int kc = ks * 8;
        uint32_t a0 = ao[r0 * AP + kc + cq];
        uint32_t a1 = ao[(r0 + 8) * AP + kc + cq];
        uint32_t a2 = ao[r0 * AP + kc + cq + 4];
        uint32_t a3 = ao[(r0 + 8) * AP + kc + cq + 4];
        #pragma unroll
        for (int t = 0; t < 8; t++) {
            int n0 = (colbase + t * 8 + g2) * AP + kc;
            uint32_t b0 = wt[n0 + cq];
            uint32_t b1 = wt[n0 + cq + 4];
            mma_tf32(acc[t], a0, a1, a2, a3, b0, b1);
        }
    }

    #pragma unroll
    for (int t = 0; t < 8; t++) {
        int col = colbase + t * 8 + cq * 2;
        float2 bb = __ldg((const float2*)&bo[col]);
        *(float2*)&out[(size_t)(Rb + r0) * CDIM + col] =
            make_float2(acc[t][0] + bb.x, acc[t][1] + bb.y);
        *(float2*)&out[(size_t)(Rb + r0 + 8) * CDIM + col] =
            make_float2(acc[t][2] + bb.x, acc[t][3] + bb.y);
    }
}

// =====================================================================
extern "C" void kernel_launch(void* const* d_in, const int* in_sizes, int n_in,
                              void* d_out, int out_size)
{
    const float* x    = (const float*)d_in[0];
    const float* mask = (const float*)d_in[1];
    const float* lng  = (const float*)d_in[2];
    const float* lnb  = (const float*)d_in[3];
    const float* wb   = (const float*)d_in[4];
    const float* wq   = (const float*)d_in[5];
    const float* wk   = (const float*)d_in[6];
    const float* wv   = (const float*)d_in[7];
    const float* wg   = (const float*)d_in[8];
    const float* bg   = (const float*)d_in[9];
    const float* wo   = (const float*)d_in[10];
    const float* bo   = (const float*)d_in[11];
    float* out = (float*)d_out;

    cudaFuncSetAttribute(kA, cudaFuncAttributeMaxDynamicSharedMemorySize, SMEM_A);
    cudaFuncSetAttribute(kB, cudaFuncAttributeMaxDynamicSharedMemorySize, SMEM_B);
    cudaFuncSetAttribute(kC, cudaFuncAttributeMaxDynamicSharedMemorySize, SMEM_C);

    kA<<<NN / 128, 512, SMEM_A>>>(x, lng, lnb, wb, wq, wk, wv, wg, bg);
    kB<<<dim3(NRES, NH), 256, SMEM_B>>>(mask);
    kC<<<NN / 128, 512, SMEM_C>>>(wo, bo, out);
}

// round 9
// speedup vs baseline: 1.9397x; 1.0925x over previous
#include <cuda_runtime.h>
#include <cstdint>

#define NRES 320
#define CDIM 128
#define NH 4
#define DH 32
#define NN (NRES*NRES)
#define AP 132   // padded row stride for MMA smem tiles

// ---------- tf32 mma helpers ----------
__device__ __forceinline__ uint32_t f2tf(float f) {
    uint32_t u; asm("cvt.rna.tf32.f32 %0, %1;" : "=r"(u) : "f"(f)); return u;
}
__device__ __forceinline__ void mma_tf32(float* d,
    uint32_t a0, uint32_t a1, uint32_t a2, uint32_t a3,
    uint32_t b0, uint32_t b1)
{
    asm volatile(
        "mma.sync.aligned.m16n8k8.row.col.f32.tf32.tf32.f32 "
        "{%0,%1,%2,%3}, {%4,%5,%6,%7}, {%8,%9}, {%0,%1,%2,%3};"
        : "+f"(d[0]), "+f"(d[1]), "+f"(d[2]), "+f"(d[3])
        : "r"(a0), "r"(a1), "r"(a2), "r"(a3), "r"(b0), "r"(b1));
}

// -------- device scratch --------
__device__ float g_q   [(size_t)NRES*NH*NRES*DH];   // [i][h][j][d]
__device__ float g_k   [(size_t)NRES*NH*NRES*DH];
__device__ float g_v   [(size_t)NRES*NH*NRES*DH];
__device__ float g_gate[(size_t)NRES*NH*NRES*DH];
__device__ float g_og  [(size_t)NN*CDIM];
__device__ float g_bias[(size_t)NH*NN];             // [h][q][j]
__device__ uint32_t g_wt[5*128*128];                // transposed tf32 weights [s][n][k]

// =====================================================================
// Kernel W: one-shot transpose+convert of the 5 weight matrices.
// =====================================================================
__global__ __launch_bounds__(256, 4) void kW(
    const float* __restrict__ wq, const float* __restrict__ wk,
    const float* __restrict__ wv, const float* __restrict__ wg,
    const float* __restrict__ wo)
{
    int idx = blockIdx.x * 256 + threadIdx.x;    // 5*16384 total
    int s = idx >> 14, r = idx & 16383;
    int n = r >> 7, k = r & 127;
    const float* W = (s == 0) ? wq : (s == 1) ? wk : (s == 2) ? wv
                   : (s == 3) ? wg : wo;
    g_wt[idx] = f2tf(W[k * 128 + n]);
}

// =====================================================================
// Kernel A (tensor, 1024 thr): LN + q/k/v/gate projections + tri bias.
// 128 rows/block, 32 warps: warp = (row-group 0..7, col-quarter 0..3).
// 2-term split-A tf32 MMA; W staged conflict-free from g_wt.
// =====================================================================
#define KA_AHI 0
#define KA_ALO (KA_AHI + 128*AP)
#define KA_WT  (KA_ALO + 128*AP)
#define KA_SG  (KA_WT  + 128*AP)
#define KA_SB  (KA_SG + 128)
#define KA_WB  (KA_SB + 128)
#define SMEM_A ((KA_WB + 512) * 4)

__global__ __launch_bounds__(1024, 1) void kA(
    const float* __restrict__ x,   const float* __restrict__ lng,
    const float* __restrict__ lnb, const float* __restrict__ wb,
    const float* __restrict__ bg)
{
    extern __shared__ float sm[];
    float* ahi_f = sm + KA_AHI;
    float* alo_f = sm + KA_ALO;
    float* sg    = sm + KA_SG;
    float* sb    = sm + KA_SB;
    float* wbs   = sm + KA_WB;
    uint32_t* ahi = (uint32_t*)ahi_f;
    uint32_t* alo = (uint32_t*)alo_f;
    uint32_t* wt  = (uint32_t*)(sm + KA_WT);

    int tid = threadIdx.x, lane = tid & 31, w = tid >> 5;
    int g2 = lane >> 2, cq = lane & 3;
    int rw = w & 7, nc = w >> 3;
    int colbase = nc * 32;
    int Rb = blockIdx.x * 128;

    if (tid < 128) { sg[tid] = lng[tid]; sb[tid] = lnb[tid]; }
    if (tid >= 128 && tid < 640) wbs[tid - 128] = wb[tid - 128];
    if (tid >= 640 && tid < 768) { /* idle */ }

    // ---- layernorm: 8 threads per row (16 elems each) ----
    int row = tid >> 3, sub = tid & 7;
    float xv[16];
    const float* xr = x + (size_t)(Rb + row) * CDIM + sub * 16;
    #pragma unroll
    for (int m4 = 0; m4 < 4; m4++) {
        float4 t = *(const float4*)(xr + m4 * 4);
        xv[m4*4+0] = t.x; xv[m4*4+1] = t.y; xv[m4*4+2] = t.z; xv[m4*4+3] = t.w;
    }
    float sum = 0.f, sq = 0.f;
    #pragma unroll
    for (int m = 0; m < 16; m++) { sum += xv[m]; sq += xv[m]*xv[m]; }
    #pragma unroll
    for (int off = 4; off >= 1; off >>= 1) {
        sum += __shfl_xor_sync(0xffffffffu, sum, off, 8);
        sq  += __shfl_xor_sync(0xffffffffu, sq,  off, 8);
    }
    float mu = sum * (1.f / CDIM);
    float rs = rsqrtf(sq * (1.f / CDIM) - mu * mu + 1e-5f);

    __syncthreads();   // sg/sb/wbs ready
    #pragma unroll
    for (int m = 0; m < 16; m++) {
        int c = sub * 16 + m;
        float val = (xv[m] - mu) * rs * sg[c] + sb[c];
        uint32_t hb = f2tf(val);
        ahi[row * AP + c] = hb;
        alo[row * AP + c] = f2tf(val - __uint_as_float(hb));
    }
    __syncthreads();   // A ready

    // ---- triangle bias: 512 items on first 512 threads ----
    if (tid < 512) {
        int r = tid >> 2, h2 = tid & 3;
        float acc = 0.f;
        #pragma unroll 8
        for (int kk = 0; kk < CDIM; kk++)
            acc += (ahi_f[r * AP + kk] + alo_f[r * AP + kk]) * wbs[kk * NH + h2];
        g_bias[(size_t)h2 * NN + Rb + r] = acc;
    }

    // ---- 4 projection chunks ----
    int r0 = (rw << 4) + g2;
    int R0 = Rb + r0, R1 = R0 + 8;
    int i0 = R0 / NRES, j0 = R0 - i0 * NRES;
    int i1 = R1 / NRES, j1 = R1 - i1 * NRES;

    #pragma unroll 1
    for (int s = 0; s < 4; s++) {
        // stage Wt (already transposed tf32): conflict-free uint4 copy
        const uint4* src = (const uint4*)(g_wt + s * 16384);
        #pragma unroll
        for (int i = 0; i < 4; i++) {
            int idx4 = tid + i * 1024;
            int n = idx4 >> 5, k4 = idx4 & 31;
            uint4 vv = __ldg(&src[idx4]);
            *(uint4*)&wt[n * AP + k4 * 4] = vv;
        }
        __syncthreads();

        float acc[4][4];
        #pragma unroll
        for (int t = 0; t < 4; t++)
            #pragma unroll
            for (int e = 0; e < 4; e++) acc[t][e] = 0.f;

        #pragma unroll 4
        for (int ks = 0; ks < 16; ks++) {
            int kc = ks * 8;
            uint32_t h0 = ahi[r0 * AP + kc + cq];
            uint32_t h1 = ahi[(r0 + 8) * AP + kc + cq];
            uint32_t h2_ = ahi[r0 * AP + kc + cq + 4];
            uint32_t h3 = ahi[(r0 + 8) * AP + kc + cq + 4];
            uint32_t l0 = alo[r0 * AP + kc + cq];
            uint32_t l1 = alo[(r0 + 8) * AP + kc + cq];
            uint32_t l2 = alo[r0 * AP + kc + cq + 4];
            uint32_t l3 = alo[(r0 + 8) * AP + kc + cq + 4];
            #pragma unroll
            for (int t = 0; t < 4; t++) {
                int n0 = (colbase + t * 8 + g2) * AP + kc;
                uint32_t b0 = wt[n0 + cq];
                uint32_t b1 = wt[n0 + cq + 4];
                mma_tf32(acc[t], h0, h1, h2_, h3, b0, b1);
                mma_tf32(acc[t], l0, l1, l2, l3, b0, b1);
            }
        }

        // epilogue
        if (s == 0) {
            #pragma unroll
            for (int t = 0; t < 4; t++)
                #pragma unroll
                for (int e = 0; e < 4; e++) acc[t][e] *= 0.17677669529663687f;
        }
        if (s == 3) {
            #pragma unroll
            for (int t = 0; t < 4; t++) {
                int col = colbase + t * 8 + cq * 2;
                float2 bgv = __ldg((const float2*)&bg[col]);
                acc[t][0] = 1.f / (1.f + __expf(-(acc[t][0] + bgv.x)));
                acc[t][1] = 1.f / (1.f + __expf(-(acc[t][1] + bgv.y)));
                acc[t][2] = 1.f / (1.f + __expf(-(acc[t][2] + bgv.x)));
                acc[t][3] = 1.f / (1.f + __expf(-(acc[t][3] + bgv.y)));
            }
        }
        float* dst = (s == 0) ? g_q : (s == 1) ? g_k : (s == 2) ? g_v : g_gate;
        #pragma unroll
        for (int t = 0; t < 4; t++) {
            int col = colbase + t * 8 + cq * 2;
            int h = col >> 5, d = col & 31;
            *(float2*)&dst[(((size_t)i0 * NH + h) * NRES + j0) * DH + d] =
                make_float2(acc[t][0], acc[t][1]);
            *(float2*)&dst[(((size_t)i1 * NH + h) * NRES + j1) * DH + d] =
                make_float2(acc[t][2], acc[t][3]);
        }
        __syncthreads();   // protect wt overwrite
    }
}

// =====================================================================
// Kernel B: attention per (i,h) using tf32 mma.sync (unchanged from R5)
// =====================================================================
#define KS_OFF   0
#define VS_OFF   (KS_OFF + 320*36)
#define QS_OFF   (VS_OFF + 320*36)
#define PS_OFF   (QS_OFF + 64*36)
#define MSK_OFF  (PS_OFF + 8*16*164)
#define RED_OFF  (MSK_OFF + 320)
#define OPART_OFF (RED_OFF + 8*16*2)
#define SMEM_B   ((OPART_OFF + 4*16*32) * 4)

__global__ __launch_bounds__(256, 1) void kB(const float* __restrict__ mask)
{
    extern __shared__ float sm[];
    uint32_t* ksu = (uint32_t*)(sm + KS_OFF);
    uint32_t* vsu = (uint32_t*)(sm + VS_OFF);
    uint32_t* qsu = (uint32_t*)(sm + QS_OFF);
    uint32_t* psu = (uint32_t*)(sm + PS_OFF);
    float* msk   = sm + MSK_OFF;
    float* red   = sm + RED_OFF;
    float* opart = sm + OPART_OFF;

    int i = blockIdx.x, h = blockIdx.y;
    int tid = threadIdx.x, lane = tid & 31, w = tid >> 5;
    int p2 = w >> 1, half = w & 1;
    int khalf = half * 160;
    int g = lane >> 2, c = lane & 3;

    size_t base = ((size_t)i * NH + h) * (NRES * DH);
    const float* kg = g_k    + base;
    const float* qg = g_q    + base;
    const float* vg = g_v    + base;
    const float* gg = g_gate + base;

    for (int idx = tid; idx < NRES * DH; idx += 256) {
        int kk = idx >> 5, d = idx & 31;
        ksu[kk * 36 + d] = f2tf(kg[idx]);
        vsu[kk * 36 + d] = f2tf(vg[idx]);
    }
    for (int idx = tid; idx < NRES; idx += 256)
        msk[idx] = 1.0e9f * (mask[(size_t)i * NRES + idx] - 1.f);

    const float* bias_h = g_bias + (size_t)h * NN;
    uint32_t* pw = psu + w * 16 * 164;

    __syncthreads();

    #pragma unroll 1
    for (int p = 0; p < 5; p++) {
        int qpass = p * 64;
        int qsub  = p2 * 16;
        int qbase = qpass + qsub;

        for (int idx = tid; idx < 64 * DH; idx += 256) {
            int r = idx >> 5, d = idx & 31;
            qsu[r * 36 + d] = f2tf(qg[(qpass + r) * DH + d]);
        }
        __syncthreads();

        float s[20][4];
        #pragma unroll
        for (int t = 0; t < 20; t++)
            #pragma unroll
            for (int e = 0; e < 4; e++) s[t][e] = 0.f;

        #pragma unroll
        for (int ds = 0; ds < 4; ds++) {
            int dc = ds * 8;
            uint32_t a0 = qsu[(qsub + g)     * 36 + dc + c];
            uint32_t a1 = qsu[(qsub + g + 8) * 36 + dc + c];
            uint32_t a2 = qsu[(qsub + g)     * 36 + dc + c + 4];
            uint32_t a3 = qsu[(qsub + g + 8) * 36 + dc + c + 4];
            #pragma unroll
            for (int t = 0; t < 20; t++) {
                int n0 = (khalf + t * 8 + g) * 36 + dc;
                uint32_t b0 = ksu[n0 + c];
                uint32_t b1 = ksu[n0 + c + 4];
                mma_tf32(s[t], a0, a1, a2, a3, b0, b1);
            }
        }

        int row0 = qbase + g, row1 = row0 + 8;
        #pragma unroll
        for (int t = 0; t < 20; t++) {
            int col = khalf + t * 8 + c * 2;
            float2 mk = *(const float2*)&msk[col];
            float2 bA = __ldg((const float2*)&bias_h[(size_t)row0 * NRES + col]);
            float2 bB = __ldg((const float2*)&bias_h[(size_t)row1 * NRES + col]);
            s[t][0] += bA.x + mk.x;  s[t][1] += bA.y + mk.y;
            s[t][2] += bB.x + mk.x;  s[t][3] += bB.y + mk.y;
        }

        float mA = -1e30f, mB = -1e30f;
        #pragma unroll
        for (int t = 0; t < 20; t++) {
            mA = fmaxf(mA, fmaxf(s[t][0], s[t][1]));
            mB = fmaxf(mB, fmaxf(s[t][2], s[t][3]));
        }
        mA = fmaxf(mA, __shfl_xor_sync(0xffffffffu, mA, 1));
        mB = fmaxf(mB, __shfl_xor_sync(0xffffffffu, mB, 1));
        mA = fmaxf(mA, __shfl_xor_sync(0xffffffffu, mA, 2));
        mB = fmaxf(mB, __shfl_xor_sync(0xffffffffu, mB, 2));

        float sA = 0.f, sB = 0.f;
        #pragma unroll
        for (int t = 0; t < 20; t++) {
            s[t][0] = __expf(s[t][0] - mA); sA += s[t][0];
            s[t][1] = __expf(s[t][1] - mA); sA += s[t][1];
            s[t][2] = __expf(s[t][2] - mB); sB += s[t][2];
            s[t][3] = __expf(s[t][3] - mB); sB += s[t][3];
        }
        sA += __shfl_xor_sync(0xffffffffu, sA, 1);
        sB += __shfl_xor_sync(0xffffffffu, sB, 1);
        sA += __shfl_xor_sync(0xffffffffu, sA, 2);
        sB += __shfl_xor_sync(0xffffffffu, sB, 2);

        if (c == 0) {
            red[(w * 16 + g)     * 2]     = mA;
            red[(w * 16 + g)     * 2 + 1] = sA;
            red[(w * 16 + g + 8) * 2]     = mB;
            red[(w * 16 + g + 8) * 2 + 1] = sB;
        }
        __syncthreads();

        int wo = w ^ 1;
        float moA = red[(wo * 16 + g) * 2],     soA = red[(wo * 16 + g) * 2 + 1];
        float moB = red[(wo * 16 + g + 8) * 2], soB = red[(wo * 16 + g + 8) * 2 + 1];
        float MA = fmaxf(mA, moA), MB = fmaxf(mB, moB);
        float eA = __expf(mA - MA), eB = __expf(mB - MB);
        float facA = eA / (sA * eA + soA * __expf(moA - MA));
        float facB = eB / (sB * eB + soB * __expf(moB - MB));

        #pragma unroll
        for (int t = 0; t < 20; t++) {
            int kl = t * 8 + c * 2;
            uint32_t p0 = f2tf(s[t][0] * facA);
            uint32_t p1 = f2tf(s[t][1] * facA);
            uint32_t p2_ = f2tf(s[t][2] * facB);
            uint32_t p3 = f2tf(s[t][3] * facB);
            *(uint2*)&pw[g * 164 + kl]       = make_uint2(p0, p1);
            *(uint2*)&pw[(g + 8) * 164 + kl] = make_uint2(p2_, p3);
        }
        __syncwarp();

        float o[4][4];
        #pragma unroll
        for (int t = 0; t < 4; t++)
            #pragma unroll
            for (int e = 0; e < 4; e++) o[t][e] = 0.f;

        #pragma unroll 4
        for (int ks = 0; ks < 20; ks++) {
            int kc = ks * 8;
            uint32_t a0 = pw[g * 164 + kc + c];
            uint32_t a1 = pw[(g + 8) * 164 + kc + c];
            uint32_t a2 = pw[g * 164 + kc + c + 4];
            uint32_t a3 = pw[(g + 8) * 164 + kc + c + 4];
            int vr0 = (khalf + kc + c) * 36;
            int vr1 = (khalf + kc + c + 4) * 36;
            #pragma unroll
            for (int t = 0; t < 4; t++) {
                uint32_t b0 = vsu[vr0 + t * 8 + g];
                uint32_t b1 = vsu[vr1 + t * 8 + g];
                mma_tf32(o[t], a0, a1, a2, a3, b0, b1);
            }
        }

        if (half) {
            #pragma unroll
            for (int t = 0; t < 4; t++) {
                int col = t * 8 + c * 2;
                *(float2*)&opart[(p2 * 16 + g) * 32 + col]     = make_float2(o[t][0], o[t][1]);
                *(float2*)&opart[(p2 * 16 + g + 8) * 32 + col] = make_float2(o[t][2], o[t][3]);
            }
        }
        __syncthreads();
        if (!half) {
            #pragma unroll
            for (int t = 0; t < 4; t++) {
                int col = t * 8 + c * 2;
                float2 qa = *(const float2*)&opart[(p2 * 16 + g) * 32 + col];
                float2 qb = *(const float2*)&opart[(p2 * 16 + g + 8) * 32 + col];
                float2 gA = __ldg((const float2*)&gg[row0 * 32 + col]);
                float2 gB = __ldg((const float2*)&gg[row1 * 32 + col]);
                float2 rA = make_float2((o[t][0] + qa.x) * gA.x, (o[t][1] + qa.y) * gA.y);
                float2 rB = make_float2((o[t][2] + qb.x) * gB.x, (o[t][3] + qb.y) * gB.y);
                *(float2*)&g_og[((size_t)i * NRES + row0) * CDIM + h * DH + col] = rA;
                *(float2*)&g_og[((size_t)i * NRES + row1) * CDIM + h * DH + col] = rB;
            }
        }
        __syncthreads();
    }
}

// =====================================================================
// Kernel C (tensor, 1024 thr): out = og @ wo + bo. 128 rows/block.
// =====================================================================
#define KC_A  0
#define KC_WT (KC_A + 128*AP)
#define SMEM_C ((KC_WT + 128*AP) * 4)

__global__ __launch_bounds__(1024, 1) void kC(
    const float* __restrict__ bo, float* __restrict__ out)
{
    extern __shared__ float sm[];
    uint32_t* ao = (uint32_t*)(sm + KC_A);
    uint32_t* wt = (uint32_t*)(sm + KC_WT);

    int tid = threadIdx.x, lane = tid & 31, w = tid >> 5;
    int g2 = lane >> 2, cq = lane & 3;
    int rw = w & 7, nc = w >> 3;
    int colbase = nc * 32;
    int Rb = blockIdx.x * 128;

    // stage A (og -> tf32) and W (pre-converted) conflict-free
    const uint4* wsrc = (const uint4*)(g_wt + 4 * 16384);
    const float4* asrc = (const float4*)(g_og + (size_t)Rb * CDIM);
    #pragma unroll
    for (int i = 0; i < 4; i++) {
        int idx4 = tid + i * 1024;
        int n = idx4 >> 5, k4 = idx4 & 31;
        uint4 wv = __ldg(&wsrc[idx4]);
        *(uint4*)&wt[n * AP + k4 * 4] = wv;
        float4 av = asrc[idx4];
        uint4 at;
        at.x = f2tf(av.x); at.y = f2tf(av.y); at.z = f2tf(av.z); at.w = f2tf(av.w);
        *(uint4*)&ao[n * AP + k4 * 4] = at;
    }
    __syncthreads();

    int r0 = (rw << 4) + g2;

    float acc[4][4];
    #pragma unroll
    for (int t = 0; t < 4; t++)
        #pragma unroll
        for (int e = 0; e < 4; e++) acc[t][e] = 0.f;

    #pragma unroll 4
    for (int ks = 0; ks < 16; ks++) {
        int kc = ks * 8;
        uint32_t a0 = ao[r0 * AP + kc + cq];
        uint32_t a1 = ao[(r0 + 8) * AP + kc + cq];
        uint32_t a2 = ao[r0 * AP + kc + cq + 4];
        uint32_t a3 = ao[(r0 + 8) * AP + kc + cq + 4];
        #pragma unroll
        for (int t = 0; t < 4; t++) {
            int n0 = (colbase + t * 8 + g2) * AP + kc;
            uint32_t b0 = wt[n0 + cq];
            uint32_t b1 = wt[n0 + cq + 4];
            mma_tf32(acc[t], a0, a1, a2, a3, b0, b1);
        }
    }

    #pragma unroll
    for (int t = 0; t < 4; t++) {
        int col = colbase + t * 8 + cq * 2;
        float2 bb = __ldg((const float2*)&bo[col]);
        *(float2*)&out[(size_t)(Rb + r0) * CDIM + col] =
            make_float2(acc[t][0] + bb.x, acc[t][1] + bb.y);
        *(float2*)&out[(size_t)(Rb + r0 + 8) * CDIM + col] =
            make_float2(acc[t][2] + bb.x, acc[t][3] + bb.y);
    }
}

// =====================================================================
extern "C" void kernel_launch(void* const* d_in, const int* in_sizes, int n_in,
                              void* d_out, int out_size)
{
    const float* x    = (const float*)d_in[0];
    const float* mask = (const float*)d_in[1];
    const float* lng  = (const float*)d_in[2];
    const float* lnb  = (const float*)d_in[3];
    const float* wb   = (const float*)d_in[4];
    const float* wq   = (const float*)d_in[5];
    const float* wk   = (const float*)d_in[6];
    const float* wv   = (const float*)d_in[7];
    const float* wg   = (const float*)d_in[8];
    const float* bg   = (const float*)d_in[9];
    const float* wo   = (const float*)d_in[10];
    const float* bo   = (const float*)d_in[11];
    float* out = (float*)d_out;

    cudaFuncSetAttribute(kA, cudaFuncAttributeMaxDynamicSharedMemorySize, SMEM_A);
    cudaFuncSetAttribute(kB, cudaFuncAttributeMaxDynamicSharedMemorySize, SMEM_B);
    cudaFuncSetAttribute(kC, cudaFuncAttributeMaxDynamicSharedMemorySize, SMEM_C);

    kW<<<320, 256>>>(wq, wk, wv, wg, wo);
    kA<<<NN / 128, 1024, SMEM_A>>>(x, lng, lnb, wb, bg);
    kB<<<dim3(NRES, NH), 256, SMEM_B>>>(mask);
    kC<<<NN / 128, 1024, SMEM_C>>>(bo, out);
}